// round 15
// baseline (speedup 1.0000x reference)
#include <cuda_runtime.h>
#include <cuda_bf16.h>
#include <math.h>
#include <stdint.h>

#define NN 65536
#define EE 524288
// dims: OBS=256 HID=512 MID=256 LSTM=256 DOUT=128 DLAST=128 RFM=256 LH=256 ACT=8

typedef __nv_bfloat16 bf16;

// ---------------- scratch (device globals; no allocation allowed) -------------
__device__ __align__(16) bf16 g_obsH[NN * 256], g_obsL[NN * 256];
__device__ __align__(16) bf16 g_h0H[NN * 256],  g_h0L[NN * 256];
__device__ __align__(16) bf16 g_t1H[NN * 512],  g_t1L[NN * 512];
__device__ __align__(16) bf16 g_xH[NN * 256],   g_xL[NN * 256];
__device__ __align__(16) bf16 g_rhH[NN * 256],  g_rhL[NN * 256];
__device__ __align__(16) bf16 g_nfH[NN * 128],  g_nfL[NN * 128];
__device__ __align__(16) bf16 g_UVH[NN * 512],  g_UVL[NN * 512];   // [U | V]
__device__ __align__(16) bf16 g_aHH[NN * 256],  g_aHL[NN * 256];
__device__ __align__(16) bf16 g_aEH[NN * 128],  g_aEL[NN * 128];
__device__ __align__(16) bf16 g_nhH[NN * 256],  g_nhL[NN * 256];
__device__ __align__(16) bf16 g_n2H[NN * 128],  g_n2L[NN * 128];
__device__ __align__(16) bf16 g_r1H[NN * 256],  g_r1L[NN * 256];
// weight planes (wih/whh gate-interleaved row' = unit*4+gate; wuv = [weL;weR])
__device__ __align__(16) bf16 g_w1aH[512 * 256],  g_w1aL[512 * 256];
__device__ __align__(16) bf16 g_w1bH[256 * 512],  g_w1bL[256 * 512];
__device__ __align__(16) bf16 g_wihH[1024 * 256], g_wihL[1024 * 256];
__device__ __align__(16) bf16 g_whhH[1024 * 256], g_whhL[1024 * 256];
__device__ __align__(16) bf16 g_w1H[128 * 256],   g_w1L[128 * 256];
__device__ __align__(16) bf16 g_wuvH[512 * 128],  g_wuvL[512 * 128];
__device__ __align__(16) bf16 g_we2H[128 * 256],  g_we2L[128 * 256];
__device__ __align__(16) bf16 g_wnH[256 * 256],   g_wnL[256 * 256];
__device__ __align__(16) bf16 g_wn2H[128 * 256],  g_wn2L[128 * 256];
__device__ __align__(16) bf16 g_wrH[256 * 128],   g_wrL[256 * 128];
__device__ float g_bg[1024];         // permuted combined gate bias
__device__ float g_buv[512];         // [be | 0]
// misc
__device__ float g_deg[NN];
__device__ int g_cnt[NN];
__device__ int g_csr[NN];
__device__ int g_cur[NN];
__device__ int g_srcv[EE];
__device__ int g_bsum[256];

// ---------------------------- helpers -----------------------------------------
__device__ __forceinline__ uint32_t sm2u(const void* p) {
    return (uint32_t)__cvta_generic_to_shared(p);
}
__device__ __forceinline__ uint32_t pk(bf16 a, bf16 b) {
    return (uint32_t)__bfloat16_as_ushort(a) |
           ((uint32_t)__bfloat16_as_ushort(b) << 16);
}
__device__ __forceinline__ void split2(float a, float b, uint32_t& hi, uint32_t& lo) {
    const bf16 ha = __float2bfloat16_rn(a), hb = __float2bfloat16_rn(b);
    hi = pk(ha, hb);
    lo = pk(__float2bfloat16_rn(a - __bfloat162float(ha)),
            __float2bfloat16_rn(b - __bfloat162float(hb)));
}
__device__ __forceinline__ void mma16(float* d, const uint32_t* a, const uint32_t* b) {
    asm("mma.sync.aligned.m16n8k16.row.col.f32.bf16.bf16.f32 "
        "{%0,%1,%2,%3}, {%4,%5,%6,%7}, {%8,%9}, {%0,%1,%2,%3};"
        : "+f"(d[0]), "+f"(d[1]), "+f"(d[2]), "+f"(d[3])
        : "r"(a[0]), "r"(a[1]), "r"(a[2]), "r"(a[3]), "r"(b[0]), "r"(b[1]));
}
__device__ __forceinline__ void ldsm4(uint32_t* r, uint32_t addr) {
    asm volatile(
        "ldmatrix.sync.aligned.m8n8.x4.shared.b16 {%0,%1,%2,%3}, [%4];"
        : "=r"(r[0]), "=r"(r[1]), "=r"(r[2]), "=r"(r[3]) : "r"(addr));
}
__device__ __forceinline__ void cpa16(uint32_t s, const void* g) {
    asm volatile("cp.async.cg.shared.global [%0], [%1], 16;" :: "r"(s), "l"(g));
}
__device__ __forceinline__ void cpcommit() {
    asm volatile("cp.async.commit_group;" ::: "memory");
}
template <int N>
__device__ __forceinline__ void cpwait() {
    asm volatile("cp.async.wait_group %0;" :: "n"(N) : "memory");
}
__device__ __forceinline__ float sigm(float x) {
    return __fdividef(1.f, 1.f + __expf(-x));
}
__device__ __forceinline__ float ftanh(float x) {
    const float e = __expf(2.f * x);
    return __fdividef(e - 1.f, e + 1.f);
}

// =============================================================================
// Shared GEMM core (BM=128, BN=128, BK=64; 256 thr = 8 warps 4m x 2n)
// BK=64 halves barrier count vs BK=32; same K-step order through the tensor
// pipe per accumulator => bit-identical results. Stage = 72KB, 2 stages.
// =============================================================================
#define AP 72                       // smem pitch in bf16 (144B; conflict-free)
#define A_PL (128 * AP)             // 9216 bf16 elts per plane
#define STG_ELT (4 * A_PL)          // 36864 bf16 elts per stage (73728 B)
#define TG_SMEM (2 * STG_ELT * 2)   // 147456 bytes

__device__ __forceinline__ void tg_issue(
    const bf16* pAh, const bf16* pAl, int ldA, int rowBase,
    const bf16* pWh, const bf16* pWl, int ldW, int colBase,
    int kk0, bf16* sb, int tid)
{
#pragma unroll
    for (int i = 0; i < 4; i++) {
        const int idx = tid + 256 * i;
        const int r = idx >> 3, c8 = (idx & 7) * 8;
        const int so = r * AP + c8;
        cpa16(sm2u(sb + so),             pAh + (size_t)(rowBase + r) * ldA + kk0 + c8);
        cpa16(sm2u(sb + A_PL + so),      pAl + (size_t)(rowBase + r) * ldA + kk0 + c8);
        cpa16(sm2u(sb + 2 * A_PL + so),  pWh + (size_t)(colBase + r) * ldW + kk0 + c8);
        cpa16(sm2u(sb + 3 * A_PL + so),  pWl + (size_t)(colBase + r) * ldW + kk0 + c8);
    }
    cpcommit();
}

#define TG_MAINLOOP(ACC, DUAL_)                                                   \
    const int ncp = K >> 6, total = (DUAL_) ? 2 * ncp : ncp;                      \
    tg_issue(Ah_, Al_, ldA, rowBase, Wh_, Wl_, ldW, colBase, 0, sm, tid);         \
    _Pragma("unroll 1")                                                           \
    for (int c = 0; c < total; c++) {                                             \
        if (c + 1 < total) {                                                      \
            const int n = c + 1;                                                  \
            const int ph = (DUAL_) ? (n >= ncp) : 0;                              \
            tg_issue(ph ? A2h : Ah_, ph ? A2l : Al_, ldA, rowBase,                \
                     ph ? W2h : Wh_, ph ? W2l : Wl_, ldW, colBase,                \
                     (ph ? n - ncp : n) << 6, sm + (n & 1) * STG_ELT, tid);       \
            cpwait<1>();                                                          \
        } else {                                                                  \
            cpwait<0>();                                                          \
        }                                                                         \
        __syncthreads();                                                          \
        const uint32_t base = sm2u(sm) + (uint32_t)(c & 1) * (STG_ELT * 2);       \
        _Pragma("unroll")                                                         \
        for (int kk = 0; kk < 64; kk += 16) {                                     \
            uint32_t ah[2][4], al[2][4], bh[4][4], bl[4][4];                      \
            _Pragma("unroll")                                                     \
            for (int mt = 0; mt < 2; mt++) {                                      \
                const uint32_t off =                                              \
                    (uint32_t)((wy * 32 + mt * 16 + (lane & 15)) * AP +           \
                               kk + ((lane >> 4) << 3)) * 2;                      \
                ldsm4(ah[mt], base + off);                                        \
                ldsm4(al[mt], base + 2 * A_PL + off);                             \
            }                                                                     \
            _Pragma("unroll")                                                     \
            for (int nb = 0; nb < 4; nb++) {                                      \
                const uint32_t off =                                              \
                    (uint32_t)((wx * 64 + nb * 16 + (lane & 7) +                  \
                                (((lane >> 4) & 1) << 3)) * AP +                  \
                               kk + (((lane >> 3) & 1) << 3)) * 2;                \
                ldsm4(bh[nb], base + 4 * A_PL + off);                             \
                ldsm4(bl[nb], base + 6 * A_PL + off);                             \
            }                                                                     \
            _Pragma("unroll")                                                     \
            for (int mt = 0; mt < 2; mt++)                                        \
                _Pragma("unroll")                                                 \
                for (int nb = 0; nb < 4; nb++)                                    \
                    _Pragma("unroll")                                             \
                    for (int h = 0; h < 2; h++) {                                 \
                        mma16(ACC[mt][nb][h], ah[mt], &bh[nb][2 * h]);            \
                        mma16(ACC[mt][nb][h], ah[mt], &bl[nb][2 * h]);            \
                        mma16(ACC[mt][nb][h], al[mt], &bh[nb][2 * h]);            \
                    }                                                             \
        }                                                                         \
        __syncthreads();                                                          \
    }

// =============================================================================
// Generic GEMM: C = act(A@W^T [+ A2@W2^T] + bias [+bias2]) -> hi/lo planes
// =============================================================================
template <int RELU_OUT, int DEGBIAS, int DUAL>
__global__ __launch_bounds__(256) void tg(
    const bf16* __restrict__ Ah_, const bf16* __restrict__ Al_,
    const bf16* __restrict__ A2h, const bf16* __restrict__ A2l, int ldA,
    const bf16* __restrict__ Wh_, const bf16* __restrict__ Wl_,
    const bf16* __restrict__ W2h, const bf16* __restrict__ W2l, int ldW, int K,
    const float* __restrict__ bias, const float* __restrict__ bias2,
    const float* __restrict__ deg,
    bf16* __restrict__ Ch, bf16* __restrict__ Cl, int ldC)
{
    extern __shared__ bf16 sm[];
    const int tid = threadIdx.x, warp = tid >> 5, lane = tid & 31;
    const int wy = warp >> 1, wx = warp & 1;
    const int g = lane >> 2, tg2 = lane & 3;
    const int rowBase = blockIdx.y * 128, colBase = blockIdx.x * 128;

    float acc[2][4][2][4];
#pragma unroll
    for (int a = 0; a < 2; a++)
#pragma unroll
        for (int b = 0; b < 4; b++)
#pragma unroll
            for (int c = 0; c < 2; c++)
#pragma unroll
                for (int d = 0; d < 4; d++) acc[a][b][c][d] = 0.f;

    TG_MAINLOOP(acc, DUAL)

#pragma unroll
    for (int mt = 0; mt < 2; mt++) {
        const int row = rowBase + wy * 32 + mt * 16 + g;
        const float d0 = DEGBIAS ? deg[row] : 1.f;
        const float d1 = DEGBIAS ? deg[row + 8] : 1.f;
#pragma unroll
        for (int nb = 0; nb < 4; nb++)
#pragma unroll
            for (int h = 0; h < 2; h++) {
                const int col = colBase + wx * 64 + nb * 16 + h * 8 + 2 * tg2;
                float bb0 = 0.f, bb1 = 0.f;
                if (bias)  { bb0 = bias[col];  bb1 = bias[col + 1]; }
                if (DUAL && bias2) { bb0 += bias2[col]; bb1 += bias2[col + 1]; }
                float v0 = acc[mt][nb][h][0] + d0 * bb0;
                float v1 = acc[mt][nb][h][1] + d0 * bb1;
                float v2 = acc[mt][nb][h][2] + d1 * bb0;
                float v3 = acc[mt][nb][h][3] + d1 * bb1;
                if (RELU_OUT) {
                    v0 = fmaxf(v0, 0.f); v1 = fmaxf(v1, 0.f);
                    v2 = fmaxf(v2, 0.f); v3 = fmaxf(v3, 0.f);
                }
                uint32_t hi, lo;
                split2(v0, v1, hi, lo);
                *(uint32_t*)&Ch[(size_t)row * ldC + col] = hi;
                *(uint32_t*)&Cl[(size_t)row * ldC + col] = lo;
                split2(v2, v3, hi, lo);
                *(uint32_t*)&Ch[(size_t)(row + 8) * ldC + col] = hi;
                *(uint32_t*)&Cl[(size_t)(row + 8) * ldC + col] = lo;
            }
    }
}

// =============================================================================
// Fused gates GEMM + LSTM (weights gate-interleaved; tile = 128 rows x 32 units)
// =============================================================================
#define EPI_PITCH 132

__global__ __launch_bounds__(256) void tglstm(
    const bf16* __restrict__ Ah_, const bf16* __restrict__ Al_,
    const bf16* __restrict__ A2h, const bf16* __restrict__ A2l, int ldA,
    const bf16* __restrict__ Wh_, const bf16* __restrict__ Wl_,
    const bf16* __restrict__ W2h, const bf16* __restrict__ W2l, int ldW, int K,
    const float* __restrict__ bgate,
    const float* __restrict__ c0,
    float* __restrict__ h1, float* __restrict__ c1,
    bf16* __restrict__ rhh, bf16* __restrict__ rhl)
{
    extern __shared__ bf16 sm[];
    const int tid = threadIdx.x, warp = tid >> 5, lane = tid & 31;
    const int wy = warp >> 1, wx = warp & 1;
    const int g = lane >> 2, tg2 = lane & 3;
    const int rowBase = blockIdx.y * 128, colBase = blockIdx.x * 128;

    float acc[2][4][2][4];
#pragma unroll
    for (int a = 0; a < 2; a++)
#pragma unroll
        for (int b = 0; b < 4; b++)
#pragma unroll
            for (int c = 0; c < 2; c++)
#pragma unroll
                for (int d = 0; d < 4; d++) acc[a][b][c][d] = 0.f;

    TG_MAINLOOP(acc, 1)

    float* st = (float*)sm;
#pragma unroll
    for (int mt = 0; mt < 2; mt++) {
        const int row = wy * 32 + mt * 16 + g;
#pragma unroll
        for (int nb = 0; nb < 4; nb++)
#pragma unroll
            for (int h = 0; h < 2; h++) {
                const int col = wx * 64 + nb * 16 + h * 8 + 2 * tg2;
                const float b0 = bgate[colBase + col];
                const float b1 = bgate[colBase + col + 1];
                st[row * EPI_PITCH + col]           = acc[mt][nb][h][0] + b0;
                st[row * EPI_PITCH + col + 1]       = acc[mt][nb][h][1] + b1;
                st[(row + 8) * EPI_PITCH + col]     = acc[mt][nb][h][2] + b0;
                st[(row + 8) * EPI_PITCH + col + 1] = acc[mt][nb][h][3] + b1;
            }
    }
    __syncthreads();

    const int uBase = colBase >> 2;
#pragma unroll
    for (int i = 0; i < 16; i++) {
        const int idx = tid + 256 * i;
        const int r = idx >> 5, u = idx & 31;
        const float* gp = st + r * EPI_PITCH + u * 4;
        const float ig = sigm(gp[0]);
        const float fg = sigm(gp[1]);
        const float gg = ftanh(gp[2]);
        const float og = sigm(gp[3]);
        const size_t o = (size_t)(rowBase + r) * 256 + uBase + u;
        const float cv = fg * c0[o] + ig * gg;
        const float hv = og * ftanh(cv);
        c1[o] = cv;
        h1[o] = hv;
        const float rv = fmaxf(hv, 0.f);
        const bf16 hb = __float2bfloat16_rn(rv);
        rhh[o] = hb;
        rhl[o] = __float2bfloat16_rn(rv - __bfloat162float(hb));
    }
}

// =============================================================================
// megasplit: all plane splits / permutes / zeroing / biases in one kernel.
// modes: 0 plain split, 1 gate-perm (1024x256), 2 we->[weL;weR], 3 zero uint2,
//        4 gate bias (bg), 5 uv bias ([be|0])
// =============================================================================
struct Seg { const void* in; void* hi; void* lo; int n; int mode; };
struct SegT { Seg s[16]; int nseg; int total; };

__global__ __launch_bounds__(256) void megasplit(SegT T)
{
    for (int idx = blockIdx.x * 256 + threadIdx.x; idx < T.total;
         idx += gridDim.x * 256) {
        int i = idx, k = 0;
        while (i >= T.s[k].n) { i -= T.s[k].n; k++; }
        const Seg sg = T.s[k];
        if (sg.mode == 0) {
            const float4 v = ((const float4*)sg.in)[i];
            uint32_t h0, l0, h1, l1;
            split2(v.x, v.y, h0, l0);
            split2(v.z, v.w, h1, l1);
            ((uint2*)sg.hi)[i] = make_uint2(h0, h1);
            ((uint2*)sg.lo)[i] = make_uint2(l0, l1);
        } else if (sg.mode == 1) {
            const int r = i >> 6, c = i & 63;
            const int rp = (r & 255) * 4 + (r >> 8);
            const float4 v = ((const float4*)sg.in)[i];
            uint32_t h0, l0, h1, l1;
            split2(v.x, v.y, h0, l0);
            split2(v.z, v.w, h1, l1);
            ((uint2*)sg.hi)[rp * 64 + c] = make_uint2(h0, h1);
            ((uint2*)sg.lo)[rp * 64 + c] = make_uint2(l0, l1);
        } else if (sg.mode == 2) {
            const int r = i >> 6, c4 = i & 63;
            const int orow = (c4 < 32) ? r : 256 + r;
            const int oidx = orow * 32 + (c4 & 31);
            const float4 v = ((const float4*)sg.in)[i];
            uint32_t h0, l0, h1, l1;
            split2(v.x, v.y, h0, l0);
            split2(v.z, v.w, h1, l1);
            ((uint2*)sg.hi)[oidx] = make_uint2(h0, h1);
            ((uint2*)sg.lo)[oidx] = make_uint2(l0, l1);
        } else if (sg.mode == 3) {
            ((uint2*)sg.hi)[i] = make_uint2(0u, 0u);
        } else if (sg.mode == 4) {
            const float b = ((const float*)sg.in)[i] + ((const float*)sg.lo)[i];
            ((float*)sg.hi)[(i & 255) * 4 + (i >> 8)] = b;
        } else {
            ((float*)sg.hi)[i] = (i < 256) ? ((const float*)sg.in)[i] : 0.f;
        }
    }
}

// =============================================================================
// CSR build
// =============================================================================
__global__ __launch_bounds__(256) void hist_kernel(const int* __restrict__ dst,
                                                   int* __restrict__ cnt)
{
    atomicAdd(&cnt[dst[blockIdx.x * 256 + threadIdx.x]], 1);
}
__global__ __launch_bounds__(256) void scan1_kernel(
    const int* __restrict__ cnt, int* __restrict__ csr, int* __restrict__ bsum)
{
    __shared__ int s[256];
    const int t = threadIdx.x, b = blockIdx.x;
    const int v = cnt[b * 256 + t];
    s[t] = v; __syncthreads();
#pragma unroll
    for (int off = 1; off < 256; off <<= 1) {
        int x = (t >= off) ? s[t - off] : 0;
        __syncthreads();
        s[t] += x;
        __syncthreads();
    }
    csr[b * 256 + t] = s[t] - v;
    if (t == 255) bsum[b] = s[255];
}
__global__ __launch_bounds__(256) void scan3_kernel(
    int* __restrict__ csr, const int* __restrict__ bsum, int* __restrict__ cur)
{
    __shared__ int s[256];
    const int t = threadIdx.x, b = blockIdx.x;
    const int v = bsum[t];
    s[t] = v; __syncthreads();
#pragma unroll
    for (int off = 1; off < 256; off <<= 1) {
        int x = (t >= off) ? s[t - off] : 0;
        __syncthreads();
        s[t] += x;
        __syncthreads();
    }
    const int prefix = s[b] - bsum[b];
    const int i = b * 256 + t;
    const int x = csr[i] + prefix;
    csr[i] = x;
    cur[i] = x;
}
__global__ __launch_bounds__(256) void scatter_src_kernel(
    const int* __restrict__ dst, const int* __restrict__ src,
    int* __restrict__ cur, int* __restrict__ srcv)
{
    const int e = blockIdx.x * 256 + threadIdx.x;
    const int p = atomicAdd(&cur[dst[e]], 1);
    srcv[p] = src[e];
}

// =============================================================================
// Per-graph smem-tiled gather: block per 128-node graph. U rows of this graph
// are loaded once into smem as combined fp32; warps accumulate relu(U[s]+V[d]).
// Edges never cross graphs (dst = (src//128)*128 + r). Same CSR edge order per
// node as before => identical sums.
// =============================================================================
#define GA_PITCH 260
#define GA_SMEM (128 * GA_PITCH * 4)   // 133120 bytes

__device__ __forceinline__ void unpack8(uint4 h, uint4 l, float* o) {
    const __nv_bfloat162* hp = (const __nv_bfloat162*)&h;
    const __nv_bfloat162* lp = (const __nv_bfloat162*)&l;
#pragma unroll
    for (int j = 0; j < 4; j++) {
        const float2 fh = __bfloat1622float2(hp[j]);
        const float2 fl = __bfloat1622float2(lp[j]);
        o[2 * j] = fh.x + fl.x;
        o[2 * j + 1] = fh.y + fl.y;
    }
}

__global__ __launch_bounds__(256) void gather_kernel(
    const bf16* __restrict__ UVh, const bf16* __restrict__ UVl,
    const int* __restrict__ srcv,
    const int* __restrict__ csr, const int* __restrict__ cnt,
    bf16* __restrict__ aggHh, bf16* __restrict__ aggHl, float* __restrict__ deg)
{
    extern __shared__ float sU[];        // [128][GA_PITCH] combined-fp32 U tile
    const int gph = blockIdx.x;          // graph id
    const int tid = threadIdx.x;
    const int base = gph * 128;

    // load U tile: rows base..base+127, first 256 of each 512-wide UV row
    for (int idx = tid; idx < 4096; idx += 256) {
        const int r = idx >> 5, q = idx & 31;    // q = uint4 (8 bf16) index
        float u[8];
        unpack8(((const uint4*)(UVh + (size_t)(base + r) * 512))[q],
                ((const uint4*)(UVl + (size_t)(base + r) * 512))[q], u);
        float4* dp = (float4*)&sU[r * GA_PITCH + q * 8];
        dp[0] = make_float4(u[0], u[1], u[2], u[3]);
        dp[1] = make_float4(u[4], u[5], u[6], u[7]);
    }
    __syncthreads();

    const int w = tid >> 5, l = tid & 31;
#pragma unroll 1
    for (int i = 0; i < 16; i++) {
        const int d = base + w * 16 + i;
        const int start = csr[d];
        const int n = cnt[d];

        float v[8];
        unpack8(((const uint4*)(UVh + (size_t)d * 512 + 256))[l],
                ((const uint4*)(UVl + (size_t)d * 512 + 256))[l], v);
        float a[8];
#pragma unroll
        for (int j = 0; j < 8; j++) a[j] = 0.f;

        const int nw = n < 32 ? n : 32;
        int myS = 0;
        if (l < nw) myS = srcv[start + l];
        for (int e = 0; e < nw; e++) {
            const int sL = __shfl_sync(0xffffffffu, myS, e) - base;
            const float4* up = (const float4*)&sU[sL * GA_PITCH + l * 8];
            const float4 u0 = up[0], u1 = up[1];
            a[0] += fmaxf(u0.x + v[0], 0.f); a[1] += fmaxf(u0.y + v[1], 0.f);
            a[2] += fmaxf(u0.z + v[2], 0.f); a[3] += fmaxf(u0.w + v[3], 0.f);
            a[4] += fmaxf(u1.x + v[4], 0.f); a[5] += fmaxf(u1.y + v[5], 0.f);
            a[6] += fmaxf(u1.z + v[6], 0.f); a[7] += fmaxf(u1.w + v[7], 0.f);
        }
        for (int e = 32; e < n; e++) {      // rare tail (deg > 32)
            const int sL = srcv[start + e] - base;
            const float4* up = (const float4*)&sU[sL * GA_PITCH + l * 8];
            const float4 u0 = up[0], u1 = up[1];
            a[0] += fmaxf(u0.x + v[0], 0.f); a[1] += fmaxf(u0.y + v[1], 0.f);
            a[2] += fmaxf(u0.z + v[2], 0.f); a[3] += fmaxf(u0.w + v[3], 0.f);
            a[4] += fmaxf(u1.x + v[4], 0.f); a[5] += fmaxf(u1.y + v[5], 0.f);
            a[6] += fmaxf(u1.z + v[6], 0.f); a[7] += fmaxf(u1.w + v[7], 0.f);
        }

        uint4 oh, ol;
        split2(a[0], a[1], oh.x, ol.x);
        split2(a[2], a[3], oh.y, ol.y);
        split2(a[4], a[5], oh.z, ol.z);
        split2(a[6], a[7], oh.w, ol.w);
        ((uint4*)(aggHh + (size_t)d * 256))[l] = oh;
        ((uint4*)(aggHl + (size_t)d * 256))[l] = ol;
        if (l == 0) deg[d] = (float)n;
    }
}

// =============================================================================
// Readout second layer
// =============================================================================
__global__ __launch_bounds__(256) void logits_kernel(
    const bf16* __restrict__ r1h, const bf16* __restrict__ r1l,
    const float* __restrict__ wr2, const float* __restrict__ br2,
    float* __restrict__ out)
{
    __shared__ float sw[8 * 257];
    const int tid = threadIdx.x;
    for (int i = tid; i < 2048; i += 256)
        sw[(i >> 8) * 257 + (i & 255)] = wr2[i];
    __syncthreads();

    const int row = blockIdx.x * 32 + (tid >> 3);
    const int o = tid & 7;
    const __nv_bfloat162* ah = (const __nv_bfloat162*)(r1h + (size_t)row * 256);
    const __nv_bfloat162* al = (const __nv_bfloat162*)(r1l + (size_t)row * 256);
    const float* w = sw + o * 257;
    float acc = 0.f;
#pragma unroll 8
    for (int k = 0; k < 128; k++) {
        const float2 h = __bfloat1622float2(ah[k]);
        const float2 l = __bfloat1622float2(al[k]);
        acc = fmaf(h.x + l.x, w[2 * k], acc);
        acc = fmaf(h.y + l.y, w[2 * k + 1], acc);
    }
    out[(size_t)row * 8 + o] = acc + br2[o];
}

// =============================================================================
// Launcher
// =============================================================================
#define GSYM(var, sym) cudaGetSymbolAddress((void**)&var, sym)

extern "C" void kernel_launch(void* const* d_in, const int* in_sizes, int n_in,
                              void* d_out, int out_size)
{
    const float* obs  = (const float*)d_in[0];
    const float* h0   = (const float*)d_in[1];
    const float* c0   = (const float*)d_in[2];
    const int*   src  = (const int*)d_in[3];
    const int*   dst  = (const int*)d_in[4];
    const float* w1a  = (const float*)d_in[5];
    const float* b1a  = (const float*)d_in[6];
    const float* w1b  = (const float*)d_in[7];
    const float* b1b  = (const float*)d_in[8];
    const float* w_ih = (const float*)d_in[9];
    const float* b_ih = (const float*)d_in[10];
    const float* w_hh = (const float*)d_in[11];
    const float* b_hh = (const float*)d_in[12];
    const float* w1   = (const float*)d_in[13];
    const float* b1   = (const float*)d_in[14];
    const float* we   = (const float*)d_in[15];
    const float* be   = (const float*)d_in[16];
    const float* we2  = (const float*)d_in[17];
    const float* be2  = (const float*)d_in[18];
    const float* wn   = (const float*)d_in[19];
    const float* bn   = (const float*)d_in[20];
    const float* wn2  = (const float*)d_in[21];
    const float* bn2  = (const float*)d_in[22];
    const float* wr   = (const float*)d_in[23];
    const float* br   = (const float*)d_in[24];
    const float* wr2  = (const float*)d_in[25];
    const float* br2  = (const float*)d_in[26];

    float* out    = (float*)d_out;
    float* logits = out;                       // [N, 8]
    float* h1     = out + (size_t)NN * 8;      // [N, 256]
    float* c1     = h1 + (size_t)NN * 256;     // [N, 256]

    bf16 *obsH, *obsL, *h0H, *h0L, *t1H, *t1L, *xH, *xL, *rhH, *rhL,
         *nfH, *nfL, *UVH, *UVL, *aHH, *aHL, *aEH, *aEL, *nhH, *nhL,
         *n2H, *n2L, *r1H, *r1L;
    bf16 *w1aH, *w1aL, *w1bH, *w1bL, *wihH, *wihL, *whhH, *whhL, *w1H, *w1L,
         *wuvH, *wuvL, *we2H, *we2L, *wnH, *wnL, *wn2H, *wn2L, *wrH, *wrL;
    float *p_deg, *p_bg, *p_buv;
    int *p_cnt, *p_csr, *p_cur, *p_srcv, *p_bsum;

    GSYM(obsH, g_obsH); GSYM(obsL, g_obsL); GSYM(h0H, g_h0H); GSYM(h0L, g_h0L);
    GSYM(t1H, g_t1H);   GSYM(t1L, g_t1L);   GSYM(xH, g_xH);   GSYM(xL, g_xL);
    GSYM(rhH, g_rhH);   GSYM(rhL, g_rhL);
    GSYM(nfH, g_nfH);   GSYM(nfL, g_nfL);   GSYM(UVH, g_UVH); GSYM(UVL, g_UVL);
    GSYM(aHH, g_aHH);   GSYM(aHL, g_aHL);
    GSYM(aEH, g_aEH);   GSYM(aEL, g_aEL);   GSYM(nhH, g_nhH); GSYM(nhL, g_nhL);
    GSYM(n2H, g_n2H);   GSYM(n2L, g_n2L);   GSYM(r1H, g_r1H); GSYM(r1L, g_r1L);
    GSYM(w1aH, g_w1aH); GSYM(w1aL, g_w1aL); GSYM(w1bH, g_w1bH); GSYM(w1bL, g_w1bL);
    GSYM(wihH, g_wihH); GSYM(wihL, g_wihL); GSYM(whhH, g_whhH); GSYM(whhL, g_whhL);
    GSYM(w1H, g_w1H);   GSYM(w1L, g_w1L);   GSYM(wuvH, g_wuvH); GSYM(wuvL, g_wuvL);
    GSYM(we2H, g_we2H); GSYM(we2L, g_we2L); GSYM(wnH, g_wnH);   GSYM(wnL, g_wnL);
    GSYM(wn2H, g_wn2H); GSYM(wn2L, g_wn2L); GSYM(wrH, g_wrH);   GSYM(wrL, g_wrL);
    GSYM(p_bg, g_bg);   GSYM(p_buv, g_buv); GSYM(p_deg, g_deg);
    GSYM(p_cnt, g_cnt); GSYM(p_csr, g_csr); GSYM(p_cur, g_cur);
    GSYM(p_srcv, g_srcv); GSYM(p_bsum, g_bsum);

    cudaFuncSetAttribute(tg<1,0,0>, cudaFuncAttributeMaxDynamicSharedMemorySize, TG_SMEM);
    cudaFuncSetAttribute(tg<0,0,0>, cudaFuncAttributeMaxDynamicSharedMemorySize, TG_SMEM);
    cudaFuncSetAttribute(tg<0,1,0>, cudaFuncAttributeMaxDynamicSharedMemorySize, TG_SMEM);
    cudaFuncSetAttribute(tg<1,0,1>, cudaFuncAttributeMaxDynamicSharedMemorySize, TG_SMEM);
    cudaFuncSetAttribute(tglstm, cudaFuncAttributeMaxDynamicSharedMemorySize, TG_SMEM);
    cudaFuncSetAttribute(gather_kernel, cudaFuncAttributeMaxDynamicSharedMemorySize, GA_SMEM);

    const dim3 blk(256);
    const int MT = NN / 128;   // 512 row tiles

    // ---- megasplit: all splits/permutes/bias/zero ----
    SegT T;
    int seg = 0, tot = 0;
    auto addseg = [&](const void* in, void* hi, void* lo, int n, int mode) {
        T.s[seg].in = in; T.s[seg].hi = hi; T.s[seg].lo = lo;
        T.s[seg].n = n; T.s[seg].mode = mode;
        seg++; tot += n;
    };
    addseg(obs, obsH, obsL, NN * 256 / 4, 0);
    addseg(h0, h0H, h0L, NN * 256 / 4, 0);
    addseg(w_ih, wihH, wihL, 1024 * 256 / 4, 1);
    addseg(w_hh, whhH, whhL, 1024 * 256 / 4, 1);
    addseg(w1a, w1aH, w1aL, 512 * 256 / 4, 0);
    addseg(w1b, w1bH, w1bL, 256 * 512 / 4, 0);
    addseg(we, wuvH, wuvL, 256 * 256 / 4, 2);
    addseg(wn, wnH, wnL, 256 * 256 / 4, 0);
    addseg(w1, w1H, w1L, 128 * 256 / 4, 0);
    addseg(we2, we2H, we2L, 128 * 256 / 4, 0);
    addseg(wn2, wn2H, wn2L, 128 * 256 / 4, 0);
    addseg(wr, wrH, wrL, 256 * 128 / 4, 0);
    addseg(nullptr, p_cnt, nullptr, NN / 2, 3);
    addseg(b_ih, p_bg, (void*)b_hh, 1024, 4);
    addseg(be, p_buv, nullptr, 512, 5);
    T.nseg = seg; T.total = tot;
    megasplit<<<2048, blk>>>(T);

    // ---- CSR build ----
    hist_kernel<<<EE / 256, blk>>>(dst, p_cnt);
    scan1_kernel<<<256, blk>>>(p_cnt, p_csr, p_bsum);
    scan3_kernel<<<256, blk>>>(p_csr, p_bsum, p_cur);
    scatter_src_kernel<<<EE / 256, blk>>>(dst, src, p_cur, p_srcv);

    // 1. t1 = relu(obs @ w1a^T + b1a)                        [N,512] K=256
    tg<1,0,0><<<dim3(4, MT), blk, TG_SMEM>>>(obsH, obsL, nullptr, nullptr, 256,
                                             w1aH, w1aL, nullptr, nullptr, 256, 256,
                                             b1a, nullptr, nullptr, t1H, t1L, 512);
    // 2. x = t1 @ w1b^T + b1b                                [N,256] K=512
    tg<0,0,0><<<dim3(2, MT), blk, TG_SMEM>>>(t1H, t1L, nullptr, nullptr, 512,
                                             w1bH, w1bL, nullptr, nullptr, 512, 512,
                                             b1b, nullptr, nullptr, xH, xL, 256);
    // 3+4. fused gates GEMM + LSTM -> h1, c1, relu(h1) planes
    tglstm<<<dim3(8, MT), blk, TG_SMEM>>>(xH, xL, h0H, h0L, 256,
                                          wihH, wihL, whhH, whhL, 256, 256,
                                          p_bg, c0, h1, c1, rhH, rhL);
    // 5. nf = relu(h1) @ w1^T + b1                           [N,128] K=256
    tg<0,0,0><<<dim3(1, MT), blk, TG_SMEM>>>(rhH, rhL, nullptr, nullptr, 256,
                                             w1H, w1L, nullptr, nullptr, 256, 256,
                                             b1, nullptr, nullptr, nfH, nfL, 128);
    // 6. [U|V] = nf @ wuv^T + [be|0]                         [N,512] K=128
    tg<0,0,0><<<dim3(4, MT), blk, TG_SMEM>>>(nfH, nfL, nullptr, nullptr, 128,
                                             wuvH, wuvL, nullptr, nullptr, 128, 128,
                                             p_buv, nullptr, nullptr, UVH, UVL, 512);
    // 7. gather (per-graph smem tile): aggH[d] = sum relu(U[src]+V[d]); deg=cnt
    gather_kernel<<<NN / 128, blk, GA_SMEM>>>(UVH, UVL, p_srcv, p_csr, p_cnt,
                                              aHH, aHL, p_deg);
    // 8. aggE = aggH @ we2^T + deg*be2                       [N,128] K=256
    tg<0,1,0><<<dim3(1, MT), blk, TG_SMEM>>>(aHH, aHL, nullptr, nullptr, 256,
                                             we2H, we2L, nullptr, nullptr, 256, 256,
                                             be2, nullptr, p_deg, aEH, aEL, 128);
    // 9. nh = relu(nf@wnL^T + aggE@wnR^T + bn)               [N,256]
    tg<1,0,1><<<dim3(2, MT), blk, TG_SMEM>>>(nfH, nfL, aEH, aEL, 128,
                                             wnH, wnL, wnH + 128, wnL + 128, 256, 128,
                                             bn, nullptr, nullptr, nhH, nhL, 256);
    // 10. nf2 = nh @ wn2^T + bn2                             [N,128] K=256
    tg<0,0,0><<<dim3(1, MT), blk, TG_SMEM>>>(nhH, nhL, nullptr, nullptr, 256,
                                             wn2H, wn2L, nullptr, nullptr, 256, 256,
                                             bn2, nullptr, nullptr, n2H, n2L, 128);
    // 11. r1 = relu(nf2 @ wr^T + br)                         [N,256] K=128
    tg<1,0,0><<<dim3(2, MT), blk, TG_SMEM>>>(n2H, n2L, nullptr, nullptr, 128,
                                             wrH, wrL, nullptr, nullptr, 128, 128,
                                             br, nullptr, nullptr, r1H, r1L, 256);
    // 12. logits = r1 @ wr2^T + br2                          [N,8]
    logits_kernel<<<NN / 32, blk>>>(r1H, r1L, wr2, br2, logits);
}

// round 16
// speedup vs baseline: 1.0958x; 1.0958x over previous
#include <cuda_runtime.h>
#include <cuda_bf16.h>
#include <math.h>
#include <stdint.h>

#define NN 65536
#define EE 524288
// dims: OBS=256 HID=512 MID=256 LSTM=256 DOUT=128 DLAST=128 RFM=256 LH=256 ACT=8

typedef __nv_bfloat16 bf16;

// ---------------- scratch (device globals; no allocation allowed) -------------
__device__ __align__(16) bf16 g_obsH[NN * 256], g_obsL[NN * 256];
__device__ __align__(16) bf16 g_h0H[NN * 256],  g_h0L[NN * 256];
__device__ __align__(16) bf16 g_t1H[NN * 512],  g_t1L[NN * 512];
__device__ __align__(16) bf16 g_xH[NN * 256],   g_xL[NN * 256];
__device__ __align__(16) bf16 g_rhH[NN * 256],  g_rhL[NN * 256];
__device__ __align__(16) bf16 g_nfH[NN * 128],  g_nfL[NN * 128];
__device__ __align__(16) bf16 g_UVH[NN * 512],  g_UVL[NN * 512];   // [U | V]
__device__ __align__(16) bf16 g_aHH[NN * 256],  g_aHL[NN * 256];
__device__ __align__(16) bf16 g_aEH[NN * 128],  g_aEL[NN * 128];
__device__ __align__(16) bf16 g_nhH[NN * 256],  g_nhL[NN * 256];
__device__ __align__(16) bf16 g_n2H[NN * 128],  g_n2L[NN * 128];
__device__ __align__(16) bf16 g_r1H[NN * 256],  g_r1L[NN * 256];
// weight planes (wih/whh gate-interleaved row' = unit*4+gate; wuv = [weL;weR])
__device__ __align__(16) bf16 g_w1aH[512 * 256],  g_w1aL[512 * 256];
__device__ __align__(16) bf16 g_w1bH[256 * 512],  g_w1bL[256 * 512];
__device__ __align__(16) bf16 g_wihH[1024 * 256], g_wihL[1024 * 256];
__device__ __align__(16) bf16 g_whhH[1024 * 256], g_whhL[1024 * 256];
__device__ __align__(16) bf16 g_w1H[128 * 256],   g_w1L[128 * 256];
__device__ __align__(16) bf16 g_wuvH[512 * 128],  g_wuvL[512 * 128];
__device__ __align__(16) bf16 g_we2H[128 * 256],  g_we2L[128 * 256];
__device__ __align__(16) bf16 g_wnH[256 * 256],   g_wnL[256 * 256];
__device__ __align__(16) bf16 g_wn2H[128 * 256],  g_wn2L[128 * 256];
__device__ __align__(16) bf16 g_wrH[256 * 128],   g_wrL[256 * 128];
__device__ float g_bg[1024];         // permuted combined gate bias
__device__ float g_buv[512];         // [be | 0]
// misc
__device__ float g_deg[NN];
__device__ int g_cnt[NN];
__device__ int g_csr[NN];
__device__ int g_cur[NN];
__device__ int g_srcv[EE];
__device__ int g_bsum[256];

// ---------------------------- helpers -----------------------------------------
__device__ __forceinline__ uint32_t sm2u(const void* p) {
    return (uint32_t)__cvta_generic_to_shared(p);
}
__device__ __forceinline__ uint32_t pk(bf16 a, bf16 b) {
    return (uint32_t)__bfloat16_as_ushort(a) |
           ((uint32_t)__bfloat16_as_ushort(b) << 16);
}
__device__ __forceinline__ void split2(float a, float b, uint32_t& hi, uint32_t& lo) {
    const bf16 ha = __float2bfloat16_rn(a), hb = __float2bfloat16_rn(b);
    hi = pk(ha, hb);
    lo = pk(__float2bfloat16_rn(a - __bfloat162float(ha)),
            __float2bfloat16_rn(b - __bfloat162float(hb)));
}
__device__ __forceinline__ void mma16(float* d, const uint32_t* a, const uint32_t* b) {
    asm volatile(
        "mma.sync.aligned.m16n8k16.row.col.f32.bf16.bf16.f32 "
        "{%0,%1,%2,%3}, {%4,%5,%6,%7}, {%8,%9}, {%0,%1,%2,%3};"
        : "+f"(d[0]), "+f"(d[1]), "+f"(d[2]), "+f"(d[3])
        : "r"(a[0]), "r"(a[1]), "r"(a[2]), "r"(a[3]), "r"(b[0]), "r"(b[1]));
}
__device__ __forceinline__ void ldsm4(uint32_t* r, uint32_t addr) {
    asm volatile(
        "ldmatrix.sync.aligned.m8n8.x4.shared.b16 {%0,%1,%2,%3}, [%4];"
        : "=r"(r[0]), "=r"(r[1]), "=r"(r[2]), "=r"(r[3]) : "r"(addr));
}
__device__ __forceinline__ void cpa16(uint32_t s, const void* g) {
    asm volatile("cp.async.cg.shared.global [%0], [%1], 16;" :: "r"(s), "l"(g));
}
__device__ __forceinline__ void cpcommit() {
    asm volatile("cp.async.commit_group;" ::: "memory");
}
template <int N>
__device__ __forceinline__ void cpwait() {
    asm volatile("cp.async.wait_group %0;" :: "n"(N) : "memory");
}
__device__ __forceinline__ float sigm(float x) {
    return __fdividef(1.f, 1.f + __expf(-x));
}
__device__ __forceinline__ float ftanh(float x) {
    const float e = __expf(2.f * x);
    return __fdividef(e - 1.f, e + 1.f);
}

// =============================================================================
// Shared GEMM core (BM=128, BN=128, BK=32; 256 thr = 8 warps 4m x 2n)
// 80KB smem => 2 CTAs/SM resident (the R15 BK=64 variant dropped to 1 and
// regressed ~200us; this is the measured-best R11 configuration).
// =============================================================================
#define AP 40
#define STG_ELT 20480              // bf16 elements per stage (40960 B)
#define TG_SMEM (2 * STG_ELT * 2)  // 81920 bytes

__device__ __forceinline__ void tg_issue(
    const bf16* pAh, const bf16* pAl, int ldA, int rowBase,
    const bf16* pWh, const bf16* pWl, int ldW, int colBase,
    int kk0, bf16* sb, int tid)
{
#pragma unroll
    for (int i = 0; i < 2; i++) {
        const int idx = tid + 256 * i;
        const int r = idx >> 2, c8 = (idx & 3) * 8;
        const int so = r * AP + c8;
        cpa16(sm2u(sb + so),        pAh + (size_t)(rowBase + r) * ldA + kk0 + c8);
        cpa16(sm2u(sb + 5120 + so), pAl + (size_t)(rowBase + r) * ldA + kk0 + c8);
        cpa16(sm2u(sb + 10240 + so), pWh + (size_t)(colBase + r) * ldW + kk0 + c8);
        cpa16(sm2u(sb + 15360 + so), pWl + (size_t)(colBase + r) * ldW + kk0 + c8);
    }
    cpcommit();
}

#define TG_MAINLOOP(ACC, DUAL_)                                                   \
    const int ncp = K >> 5, total = (DUAL_) ? 2 * ncp : ncp;                      \
    tg_issue(Ah_, Al_, ldA, rowBase, Wh_, Wl_, ldW, colBase, 0, sm, tid);         \
    _Pragma("unroll 1")                                                           \
    for (int c = 0; c < total; c++) {                                             \
        if (c + 1 < total) {                                                      \
            const int n = c + 1;                                                  \
            const int ph = (DUAL_) ? (n >= ncp) : 0;                              \
            tg_issue(ph ? A2h : Ah_, ph ? A2l : Al_, ldA, rowBase,                \
                     ph ? W2h : Wh_, ph ? W2l : Wl_, ldW, colBase,                \
                     (ph ? n - ncp : n) << 5, sm + (n & 1) * STG_ELT, tid);       \
            cpwait<1>();                                                          \
        } else {                                                                  \
            cpwait<0>();                                                          \
        }                                                                         \
        __syncthreads();                                                          \
        const uint32_t base = sm2u(sm) + (uint32_t)(c & 1) * (STG_ELT * 2);       \
        _Pragma("unroll")                                                         \
        for (int kk = 0; kk < 32; kk += 16) {                                     \
            uint32_t ah[2][4], al[2][4], bh[4][4], bl[4][4];                      \
            _Pragma("unroll")                                                     \
            for (int mt = 0; mt < 2; mt++) {                                      \
                const uint32_t off =                                              \
                    (uint32_t)((wy * 32 + mt * 16 + (lane & 15)) * AP +           \
                               kk + ((lane >> 4) << 3)) * 2;                      \
                ldsm4(ah[mt], base + off);                                        \
                ldsm4(al[mt], base + 10240 + off);                                \
            }                                                                     \
            _Pragma("unroll")                                                     \
            for (int nb = 0; nb < 4; nb++) {                                      \
                const uint32_t off =                                              \
                    (uint32_t)((wx * 64 + nb * 16 + (lane & 7) +                  \
                                (((lane >> 4) & 1) << 3)) * AP +                  \
                               kk + (((lane >> 3) & 1) << 3)) * 2;                \
                ldsm4(bh[nb], base + 20480 + off);                                \
                ldsm4(bl[nb], base + 30720 + off);                                \
            }                                                                     \
            _Pragma("unroll")                                                     \
            for (int mt = 0; mt < 2; mt++)                                        \
                _Pragma("unroll")                                                 \
                for (int nb = 0; nb < 4; nb++)                                    \
                    _Pragma("unroll")                                             \
                    for (int h = 0; h < 2; h++) {                                 \
                        mma16(ACC[mt][nb][h], ah[mt], &bh[nb][2 * h]);            \
                        mma16(ACC[mt][nb][h], ah[mt], &bl[nb][2 * h]);            \
                        mma16(ACC[mt][nb][h], al[mt], &bh[nb][2 * h]);            \
                    }                                                             \
        }                                                                         \
        __syncthreads();                                                          \
    }

// =============================================================================
// Generic GEMM: C = act(A@W^T [+ A2@W2^T] + bias [+bias2]) -> hi/lo planes
// =============================================================================
template <int RELU_OUT, int DEGBIAS, int DUAL>
__global__ __launch_bounds__(256) void tg(
    const bf16* __restrict__ Ah_, const bf16* __restrict__ Al_,
    const bf16* __restrict__ A2h, const bf16* __restrict__ A2l, int ldA,
    const bf16* __restrict__ Wh_, const bf16* __restrict__ Wl_,
    const bf16* __restrict__ W2h, const bf16* __restrict__ W2l, int ldW, int K,
    const float* __restrict__ bias, const float* __restrict__ bias2,
    const float* __restrict__ deg,
    bf16* __restrict__ Ch, bf16* __restrict__ Cl, int ldC)
{
    extern __shared__ bf16 sm[];
    const int tid = threadIdx.x, warp = tid >> 5, lane = tid & 31;
    const int wy = warp >> 1, wx = warp & 1;
    const int g = lane >> 2, tg2 = lane & 3;
    const int rowBase = blockIdx.y * 128, colBase = blockIdx.x * 128;

    float acc[2][4][2][4];
#pragma unroll
    for (int a = 0; a < 2; a++)
#pragma unroll
        for (int b = 0; b < 4; b++)
#pragma unroll
            for (int c = 0; c < 2; c++)
#pragma unroll
                for (int d = 0; d < 4; d++) acc[a][b][c][d] = 0.f;

    TG_MAINLOOP(acc, DUAL)

#pragma unroll
    for (int mt = 0; mt < 2; mt++) {
        const int row = rowBase + wy * 32 + mt * 16 + g;
        const float d0 = DEGBIAS ? deg[row] : 1.f;
        const float d1 = DEGBIAS ? deg[row + 8] : 1.f;
#pragma unroll
        for (int nb = 0; nb < 4; nb++)
#pragma unroll
            for (int h = 0; h < 2; h++) {
                const int col = colBase + wx * 64 + nb * 16 + h * 8 + 2 * tg2;
                float bb0 = 0.f, bb1 = 0.f;
                if (bias)  { bb0 = bias[col];  bb1 = bias[col + 1]; }
                if (DUAL && bias2) { bb0 += bias2[col]; bb1 += bias2[col + 1]; }
                float v0 = acc[mt][nb][h][0] + d0 * bb0;
                float v1 = acc[mt][nb][h][1] + d0 * bb1;
                float v2 = acc[mt][nb][h][2] + d1 * bb0;
                float v3 = acc[mt][nb][h][3] + d1 * bb1;
                if (RELU_OUT) {
                    v0 = fmaxf(v0, 0.f); v1 = fmaxf(v1, 0.f);
                    v2 = fmaxf(v2, 0.f); v3 = fmaxf(v3, 0.f);
                }
                uint32_t hi, lo;
                split2(v0, v1, hi, lo);
                *(uint32_t*)&Ch[(size_t)row * ldC + col] = hi;
                *(uint32_t*)&Cl[(size_t)row * ldC + col] = lo;
                split2(v2, v3, hi, lo);
                *(uint32_t*)&Ch[(size_t)(row + 8) * ldC + col] = hi;
                *(uint32_t*)&Cl[(size_t)(row + 8) * ldC + col] = lo;
            }
    }
}

// =============================================================================
// Fused gates GEMM + LSTM (weights gate-interleaved; tile = 128 rows x 32 units)
// =============================================================================
#define EPI_PITCH 132

__global__ __launch_bounds__(256) void tglstm(
    const bf16* __restrict__ Ah_, const bf16* __restrict__ Al_,
    const bf16* __restrict__ A2h, const bf16* __restrict__ A2l, int ldA,
    const bf16* __restrict__ Wh_, const bf16* __restrict__ Wl_,
    const bf16* __restrict__ W2h, const bf16* __restrict__ W2l, int ldW, int K,
    const float* __restrict__ bgate,
    const float* __restrict__ c0,
    float* __restrict__ h1, float* __restrict__ c1,
    bf16* __restrict__ rhh, bf16* __restrict__ rhl)
{
    extern __shared__ bf16 sm[];
    const int tid = threadIdx.x, warp = tid >> 5, lane = tid & 31;
    const int wy = warp >> 1, wx = warp & 1;
    const int g = lane >> 2, tg2 = lane & 3;
    const int rowBase = blockIdx.y * 128, colBase = blockIdx.x * 128;

    float acc[2][4][2][4];
#pragma unroll
    for (int a = 0; a < 2; a++)
#pragma unroll
        for (int b = 0; b < 4; b++)
#pragma unroll
            for (int c = 0; c < 2; c++)
#pragma unroll
                for (int d = 0; d < 4; d++) acc[a][b][c][d] = 0.f;

    TG_MAINLOOP(acc, 1)

    float* st = (float*)sm;
#pragma unroll
    for (int mt = 0; mt < 2; mt++) {
        const int row = wy * 32 + mt * 16 + g;
#pragma unroll
        for (int nb = 0; nb < 4; nb++)
#pragma unroll
            for (int h = 0; h < 2; h++) {
                const int col = wx * 64 + nb * 16 + h * 8 + 2 * tg2;
                const float b0 = bgate[colBase + col];
                const float b1 = bgate[colBase + col + 1];
                st[row * EPI_PITCH + col]           = acc[mt][nb][h][0] + b0;
                st[row * EPI_PITCH + col + 1]       = acc[mt][nb][h][1] + b1;
                st[(row + 8) * EPI_PITCH + col]     = acc[mt][nb][h][2] + b0;
                st[(row + 8) * EPI_PITCH + col + 1] = acc[mt][nb][h][3] + b1;
            }
    }
    __syncthreads();

    const int uBase = colBase >> 2;
#pragma unroll
    for (int i = 0; i < 16; i++) {
        const int idx = tid + 256 * i;
        const int r = idx >> 5, u = idx & 31;
        const float* gp = st + r * EPI_PITCH + u * 4;
        const float ig = sigm(gp[0]);
        const float fg = sigm(gp[1]);
        const float gg = ftanh(gp[2]);
        const float og = sigm(gp[3]);
        const size_t o = (size_t)(rowBase + r) * 256 + uBase + u;
        const float cv = fg * c0[o] + ig * gg;
        const float hv = og * ftanh(cv);
        c1[o] = cv;
        h1[o] = hv;
        const float rv = fmaxf(hv, 0.f);
        const bf16 hb = __float2bfloat16_rn(rv);
        rhh[o] = hb;
        rhl[o] = __float2bfloat16_rn(rv - __bfloat162float(hb));
    }
}

// =============================================================================
// megasplit: all plane splits / permutes / zeroing / biases in one kernel.
// modes: 0 plain split, 1 gate-perm (1024x256), 2 we->[weL;weR], 3 zero uint2,
//        4 gate bias (bg), 5 uv bias ([be|0])
// =============================================================================
struct Seg { const void* in; void* hi; void* lo; int n; int mode; };
struct SegT { Seg s[16]; int nseg; int total; };

__global__ __launch_bounds__(256) void megasplit(SegT T)
{
    for (int idx = blockIdx.x * 256 + threadIdx.x; idx < T.total;
         idx += gridDim.x * 256) {
        int i = idx, k = 0;
        while (i >= T.s[k].n) { i -= T.s[k].n; k++; }
        const Seg sg = T.s[k];
        if (sg.mode == 0) {
            const float4 v = ((const float4*)sg.in)[i];
            uint32_t h0, l0, h1, l1;
            split2(v.x, v.y, h0, l0);
            split2(v.z, v.w, h1, l1);
            ((uint2*)sg.hi)[i] = make_uint2(h0, h1);
            ((uint2*)sg.lo)[i] = make_uint2(l0, l1);
        } else if (sg.mode == 1) {
            const int r = i >> 6, c = i & 63;
            const int rp = (r & 255) * 4 + (r >> 8);
            const float4 v = ((const float4*)sg.in)[i];
            uint32_t h0, l0, h1, l1;
            split2(v.x, v.y, h0, l0);
            split2(v.z, v.w, h1, l1);
            ((uint2*)sg.hi)[rp * 64 + c] = make_uint2(h0, h1);
            ((uint2*)sg.lo)[rp * 64 + c] = make_uint2(l0, l1);
        } else if (sg.mode == 2) {
            const int r = i >> 6, c4 = i & 63;
            const int orow = (c4 < 32) ? r : 256 + r;
            const int oidx = orow * 32 + (c4 & 31);
            const float4 v = ((const float4*)sg.in)[i];
            uint32_t h0, l0, h1, l1;
            split2(v.x, v.y, h0, l0);
            split2(v.z, v.w, h1, l1);
            ((uint2*)sg.hi)[oidx] = make_uint2(h0, h1);
            ((uint2*)sg.lo)[oidx] = make_uint2(l0, l1);
        } else if (sg.mode == 3) {
            ((uint2*)sg.hi)[i] = make_uint2(0u, 0u);
        } else if (sg.mode == 4) {
            const float b = ((const float*)sg.in)[i] + ((const float*)sg.lo)[i];
            ((float*)sg.hi)[(i & 255) * 4 + (i >> 8)] = b;
        } else {
            ((float*)sg.hi)[i] = (i < 256) ? ((const float*)sg.in)[i] : 0.f;
        }
    }
}

// =============================================================================
// CSR build
// =============================================================================
__global__ __launch_bounds__(256) void hist_kernel(const int* __restrict__ dst,
                                                   int* __restrict__ cnt)
{
    atomicAdd(&cnt[dst[blockIdx.x * 256 + threadIdx.x]], 1);
}
__global__ __launch_bounds__(256) void scan1_kernel(
    const int* __restrict__ cnt, int* __restrict__ csr, int* __restrict__ bsum)
{
    __shared__ int s[256];
    const int t = threadIdx.x, b = blockIdx.x;
    const int v = cnt[b * 256 + t];
    s[t] = v; __syncthreads();
#pragma unroll
    for (int off = 1; off < 256; off <<= 1) {
        int x = (t >= off) ? s[t - off] : 0;
        __syncthreads();
        s[t] += x;
        __syncthreads();
    }
    csr[b * 256 + t] = s[t] - v;
    if (t == 255) bsum[b] = s[255];
}
__global__ __launch_bounds__(256) void scan3_kernel(
    int* __restrict__ csr, const int* __restrict__ bsum, int* __restrict__ cur)
{
    __shared__ int s[256];
    const int t = threadIdx.x, b = blockIdx.x;
    const int v = bsum[t];
    s[t] = v; __syncthreads();
#pragma unroll
    for (int off = 1; off < 256; off <<= 1) {
        int x = (t >= off) ? s[t - off] : 0;
        __syncthreads();
        s[t] += x;
        __syncthreads();
    }
    const int prefix = s[b] - bsum[b];
    const int i = b * 256 + t;
    const int x = csr[i] + prefix;
    csr[i] = x;
    cur[i] = x;
}
__global__ __launch_bounds__(256) void scatter_src_kernel(
    const int* __restrict__ dst, const int* __restrict__ src,
    int* __restrict__ cur, int* __restrict__ srcv)
{
    const int e = blockIdx.x * 256 + threadIdx.x;
    const int p = atomicAdd(&cur[dst[e]], 1);
    srcv[p] = src[e];
}

// =============================================================================
// Per-graph smem-tiled gather: block per 128-node graph. U rows of this graph
// are loaded once into smem as combined fp32; warps accumulate relu(U[s]+V[d]).
// Edges never cross graphs. Same CSR edge order per node => identical sums.
// =============================================================================
#define GA_PITCH 260
#define GA_SMEM (128 * GA_PITCH * 4)   // 133120 bytes

__device__ __forceinline__ void unpack8(uint4 h, uint4 l, float* o) {
    const __nv_bfloat162* hp = (const __nv_bfloat162*)&h;
    const __nv_bfloat162* lp = (const __nv_bfloat162*)&l;
#pragma unroll
    for (int j = 0; j < 4; j++) {
        const float2 fh = __bfloat1622float2(hp[j]);
        const float2 fl = __bfloat1622float2(lp[j]);
        o[2 * j] = fh.x + fl.x;
        o[2 * j + 1] = fh.y + fl.y;
    }
}

__global__ __launch_bounds__(256) void gather_kernel(
    const bf16* __restrict__ UVh, const bf16* __restrict__ UVl,
    const int* __restrict__ srcv,
    const int* __restrict__ csr, const int* __restrict__ cnt,
    bf16* __restrict__ aggHh, bf16* __restrict__ aggHl, float* __restrict__ deg)
{
    extern __shared__ float sU[];        // [128][GA_PITCH] combined-fp32 U tile
    const int gph = blockIdx.x;          // graph id
    const int tid = threadIdx.x;
    const int base = gph * 128;

    // load U tile: rows base..base+127, first 256 of each 512-wide UV row
    for (int idx = tid; idx < 4096; idx += 256) {
        const int r = idx >> 5, q = idx & 31;    // q = uint4 (8 bf16) index
        float u[8];
        unpack8(((const uint4*)(UVh + (size_t)(base + r) * 512))[q],
                ((const uint4*)(UVl + (size_t)(base + r) * 512))[q], u);
        float4* dp = (float4*)&sU[r * GA_PITCH + q * 8];
        dp[0] = make_float4(u[0], u[1], u[2], u[3]);
        dp[1] = make_float4(u[4], u[5], u[6], u[7]);
    }
    __syncthreads();

    const int w = tid >> 5, l = tid & 31;
#pragma unroll 1
    for (int i = 0; i < 16; i++) {
        const int d = base + w * 16 + i;
        const int start = csr[d];
        const int n = cnt[d];

        float v[8];
        unpack8(((const uint4*)(UVh + (size_t)d * 512 + 256))[l],
                ((const uint4*)(UVl + (size_t)d * 512 + 256))[l], v);
        float a[8];
#pragma unroll
        for (int j = 0; j < 8; j++) a[j] = 0.f;

        const int nw = n < 32 ? n : 32;
        int myS = 0;
        if (l < nw) myS = srcv[start + l];
        for (int e = 0; e < nw; e++) {
            const int sL = __shfl_sync(0xffffffffu, myS, e) - base;
            const float4* up = (const float4*)&sU[sL * GA_PITCH + l * 8];
            const float4 u0 = up[0], u1 = up[1];
            a[0] += fmaxf(u0.x + v[0], 0.f); a[1] += fmaxf(u0.y + v[1], 0.f);
            a[2] += fmaxf(u0.z + v[2], 0.f); a[3] += fmaxf(u0.w + v[3], 0.f);
            a[4] += fmaxf(u1.x + v[4], 0.f); a[5] += fmaxf(u1.y + v[5], 0.f);
            a[6] += fmaxf(u1.z + v[6], 0.f); a[7] += fmaxf(u1.w + v[7], 0.f);
        }
        for (int e = 32; e < n; e++) {      // rare tail (deg > 32)
            const int sL = srcv[start + e] - base;
            const float4* up = (const float4*)&sU[sL * GA_PITCH + l * 8];
            const float4 u0 = up[0], u1 = up[1];
            a[0] += fmaxf(u0.x + v[0], 0.f); a[1] += fmaxf(u0.y + v[1], 0.f);
            a[2] += fmaxf(u0.z + v[2], 0.f); a[3] += fmaxf(u0.w + v[3], 0.f);
            a[4] += fmaxf(u1.x + v[4], 0.f); a[5] += fmaxf(u1.y + v[5], 0.f);
            a[6] += fmaxf(u1.z + v[6], 0.f); a[7] += fmaxf(u1.w + v[7], 0.f);
        }

        uint4 oh, ol;
        split2(a[0], a[1], oh.x, ol.x);
        split2(a[2], a[3], oh.y, ol.y);
        split2(a[4], a[5], oh.z, ol.z);
        split2(a[6], a[7], oh.w, ol.w);
        ((uint4*)(aggHh + (size_t)d * 256))[l] = oh;
        ((uint4*)(aggHl + (size_t)d * 256))[l] = ol;
        if (l == 0) deg[d] = (float)n;
    }
}

// =============================================================================
// Readout second layer
// =============================================================================
__global__ __launch_bounds__(256) void logits_kernel(
    const bf16* __restrict__ r1h, const bf16* __restrict__ r1l,
    const float* __restrict__ wr2, const float* __restrict__ br2,
    float* __restrict__ out)
{
    __shared__ float sw[8 * 257];
    const int tid = threadIdx.x;
    for (int i = tid; i < 2048; i += 256)
        sw[(i >> 8) * 257 + (i & 255)] = wr2[i];
    __syncthreads();

    const int row = blockIdx.x * 32 + (tid >> 3);
    const int o = tid & 7;
    const __nv_bfloat162* ah = (const __nv_bfloat162*)(r1h + (size_t)row * 256);
    const __nv_bfloat162* al = (const __nv_bfloat162*)(r1l + (size_t)row * 256);
    const float* w = sw + o * 257;
    float acc = 0.f;
#pragma unroll 8
    for (int k = 0; k < 128; k++) {
        const float2 h = __bfloat1622float2(ah[k]);
        const float2 l = __bfloat1622float2(al[k]);
        acc = fmaf(h.x + l.x, w[2 * k], acc);
        acc = fmaf(h.y + l.y, w[2 * k + 1], acc);
    }
    out[(size_t)row * 8 + o] = acc + br2[o];
}

// =============================================================================
// Launcher
// =============================================================================
#define GSYM(var, sym) cudaGetSymbolAddress((void**)&var, sym)

extern "C" void kernel_launch(void* const* d_in, const int* in_sizes, int n_in,
                              void* d_out, int out_size)
{
    const float* obs  = (const float*)d_in[0];
    const float* h0   = (const float*)d_in[1];
    const float* c0   = (const float*)d_in[2];
    const int*   src  = (const int*)d_in[3];
    const int*   dst  = (const int*)d_in[4];
    const float* w1a  = (const float*)d_in[5];
    const float* b1a  = (const float*)d_in[6];
    const float* w1b  = (const float*)d_in[7];
    const float* b1b  = (const float*)d_in[8];
    const float* w_ih = (const float*)d_in[9];
    const float* b_ih = (const float*)d_in[10];
    const float* w_hh = (const float*)d_in[11];
    const float* b_hh = (const float*)d_in[12];
    const float* w1   = (const float*)d_in[13];
    const float* b1   = (const float*)d_in[14];
    const float* we   = (const float*)d_in[15];
    const float* be   = (const float*)d_in[16];
    const float* we2  = (const float*)d_in[17];
    const float* be2  = (const float*)d_in[18];
    const float* wn   = (const float*)d_in[19];
    const float* bn   = (const float*)d_in[20];
    const float* wn2  = (const float*)d_in[21];
    const float* bn2  = (const float*)d_in[22];
    const float* wr   = (const float*)d_in[23];
    const float* br   = (const float*)d_in[24];
    const float* wr2  = (const float*)d_in[25];
    const float* br2  = (const float*)d_in[26];

    float* out    = (float*)d_out;
    float* logits = out;                       // [N, 8]
    float* h1     = out + (size_t)NN * 8;      // [N, 256]
    float* c1     = h1 + (size_t)NN * 256;     // [N, 256]

    bf16 *obsH, *obsL, *h0H, *h0L, *t1H, *t1L, *xH, *xL, *rhH, *rhL,
         *nfH, *nfL, *UVH, *UVL, *aHH, *aHL, *aEH, *aEL, *nhH, *nhL,
         *n2H, *n2L, *r1H, *r1L;
    bf16 *w1aH, *w1aL, *w1bH, *w1bL, *wihH, *wihL, *whhH, *whhL, *w1H, *w1L,
         *wuvH, *wuvL, *we2H, *we2L, *wnH, *wnL, *wn2H, *wn2L, *wrH, *wrL;
    float *p_deg, *p_bg, *p_buv;
    int *p_cnt, *p_csr, *p_cur, *p_srcv, *p_bsum;

    GSYM(obsH, g_obsH); GSYM(obsL, g_obsL); GSYM(h0H, g_h0H); GSYM(h0L, g_h0L);
    GSYM(t1H, g_t1H);   GSYM(t1L, g_t1L);   GSYM(xH, g_xH);   GSYM(xL, g_xL);
    GSYM(rhH, g_rhH);   GSYM(rhL, g_rhL);
    GSYM(nfH, g_nfH);   GSYM(nfL, g_nfL);   GSYM(UVH, g_UVH); GSYM(UVL, g_UVL);
    GSYM(aHH, g_aHH);   GSYM(aHL, g_aHL);
    GSYM(aEH, g_aEH);   GSYM(aEL, g_aEL);   GSYM(nhH, g_nhH); GSYM(nhL, g_nhL);
    GSYM(n2H, g_n2H);   GSYM(n2L, g_n2L);   GSYM(r1H, g_r1H); GSYM(r1L, g_r1L);
    GSYM(w1aH, g_w1aH); GSYM(w1aL, g_w1aL); GSYM(w1bH, g_w1bH); GSYM(w1bL, g_w1bL);
    GSYM(wihH, g_wihH); GSYM(wihL, g_wihL); GSYM(whhH, g_whhH); GSYM(whhL, g_whhL);
    GSYM(w1H, g_w1H);   GSYM(w1L, g_w1L);   GSYM(wuvH, g_wuvH); GSYM(wuvL, g_wuvL);
    GSYM(we2H, g_we2H); GSYM(we2L, g_we2L); GSYM(wnH, g_wnH);   GSYM(wnL, g_wnL);
    GSYM(wn2H, g_wn2H); GSYM(wn2L, g_wn2L); GSYM(wrH, g_wrH);   GSYM(wrL, g_wrL);
    GSYM(p_bg, g_bg);   GSYM(p_buv, g_buv); GSYM(p_deg, g_deg);
    GSYM(p_cnt, g_cnt); GSYM(p_csr, g_csr); GSYM(p_cur, g_cur);
    GSYM(p_srcv, g_srcv); GSYM(p_bsum, g_bsum);

    cudaFuncSetAttribute(tg<1,0,0>, cudaFuncAttributeMaxDynamicSharedMemorySize, TG_SMEM);
    cudaFuncSetAttribute(tg<0,0,0>, cudaFuncAttributeMaxDynamicSharedMemorySize, TG_SMEM);
    cudaFuncSetAttribute(tg<0,1,0>, cudaFuncAttributeMaxDynamicSharedMemorySize, TG_SMEM);
    cudaFuncSetAttribute(tg<1,0,1>, cudaFuncAttributeMaxDynamicSharedMemorySize, TG_SMEM);
    cudaFuncSetAttribute(tglstm, cudaFuncAttributeMaxDynamicSharedMemorySize, TG_SMEM);
    cudaFuncSetAttribute(gather_kernel, cudaFuncAttributeMaxDynamicSharedMemorySize, GA_SMEM);

    const dim3 blk(256);
    const int MT = NN / 128;   // 512 row tiles

    // ---- megasplit: all splits/permutes/bias/zero ----
    SegT T;
    int seg = 0, tot = 0;
    auto addseg = [&](const void* in, void* hi, void* lo, int n, int mode) {
        T.s[seg].in = in; T.s[seg].hi = hi; T.s[seg].lo = lo;
        T.s[seg].n = n; T.s[seg].mode = mode;
        seg++; tot += n;
    };
    addseg(obs, obsH, obsL, NN * 256 / 4, 0);
    addseg(h0, h0H, h0L, NN * 256 / 4, 0);
    addseg(w_ih, wihH, wihL, 1024 * 256 / 4, 1);
    addseg(w_hh, whhH, whhL, 1024 * 256 / 4, 1);
    addseg(w1a, w1aH, w1aL, 512 * 256 / 4, 0);
    addseg(w1b, w1bH, w1bL, 256 * 512 / 4, 0);
    addseg(we, wuvH, wuvL, 256 * 256 / 4, 2);
    addseg(wn, wnH, wnL, 256 * 256 / 4, 0);
    addseg(w1, w1H, w1L, 128 * 256 / 4, 0);
    addseg(we2, we2H, we2L, 128 * 256 / 4, 0);
    addseg(wn2, wn2H, wn2L, 128 * 256 / 4, 0);
    addseg(wr, wrH, wrL, 256 * 128 / 4, 0);
    addseg(nullptr, p_cnt, nullptr, NN / 2, 3);
    addseg(b_ih, p_bg, (void*)b_hh, 1024, 4);
    addseg(be, p_buv, nullptr, 512, 5);
    T.nseg = seg; T.total = tot;
    megasplit<<<2048, blk>>>(T);

    // ---- CSR build ----
    hist_kernel<<<EE / 256, blk>>>(dst, p_cnt);
    scan1_kernel<<<256, blk>>>(p_cnt, p_csr, p_bsum);
    scan3_kernel<<<256, blk>>>(p_csr, p_bsum, p_cur);
    scatter_src_kernel<<<EE / 256, blk>>>(dst, src, p_cur, p_srcv);

    // 1. t1 = relu(obs @ w1a^T + b1a)                        [N,512] K=256
    tg<1,0,0><<<dim3(4, MT), blk, TG_SMEM>>>(obsH, obsL, nullptr, nullptr, 256,
                                             w1aH, w1aL, nullptr, nullptr, 256, 256,
                                             b1a, nullptr, nullptr, t1H, t1L, 512);
    // 2. x = t1 @ w1b^T + b1b                                [N,256] K=512
    tg<0,0,0><<<dim3(2, MT), blk, TG_SMEM>>>(t1H, t1L, nullptr, nullptr, 512,
                                             w1bH, w1bL, nullptr, nullptr, 512, 512,
                                             b1b, nullptr, nullptr, xH, xL, 256);
    // 3+4. fused gates GEMM + LSTM -> h1, c1, relu(h1) planes
    tglstm<<<dim3(8, MT), blk, TG_SMEM>>>(xH, xL, h0H, h0L, 256,
                                          wihH, wihL, whhH, whhL, 256, 256,
                                          p_bg, c0, h1, c1, rhH, rhL);
    // 5. nf = relu(h1) @ w1^T + b1                           [N,128] K=256
    tg<0,0,0><<<dim3(1, MT), blk, TG_SMEM>>>(rhH, rhL, nullptr, nullptr, 256,
                                             w1H, w1L, nullptr, nullptr, 256, 256,
                                             b1, nullptr, nullptr, nfH, nfL, 128);
    // 6. [U|V] = nf @ wuv^T + [be|0]                         [N,512] K=128
    tg<0,0,0><<<dim3(4, MT), blk, TG_SMEM>>>(nfH, nfL, nullptr, nullptr, 128,
                                             wuvH, wuvL, nullptr, nullptr, 128, 128,
                                             p_buv, nullptr, nullptr, UVH, UVL, 512);
    // 7. gather (per-graph smem tile): aggH[d] = sum relu(U[src]+V[d]); deg=cnt
    gather_kernel<<<NN / 128, blk, GA_SMEM>>>(UVH, UVL, p_srcv, p_csr, p_cnt,
                                              aHH, aHL, p_deg);
    // 8. aggE = aggH @ we2^T + deg*be2                       [N,128] K=256
    tg<0,1,0><<<dim3(1, MT), blk, TG_SMEM>>>(aHH, aHL, nullptr, nullptr, 256,
                                             we2H, we2L, nullptr, nullptr, 256, 256,
                                             be2, nullptr, p_deg, aEH, aEL, 128);
    // 9. nh = relu(nf@wnL^T + aggE@wnR^T + bn)               [N,256]
    tg<1,0,1><<<dim3(2, MT), blk, TG_SMEM>>>(nfH, nfL, aEH, aEL, 128,
                                             wnH, wnL, wnH + 128, wnL + 128, 256, 128,
                                             bn, nullptr, nullptr, nhH, nhL, 256);
    // 10. nf2 = nh @ wn2^T + bn2                             [N,128] K=256
    tg<0,0,0><<<dim3(1, MT), blk, TG_SMEM>>>(nhH, nhL, nullptr, nullptr, 256,
                                             wn2H, wn2L, nullptr, nullptr, 256, 256,
                                             bn2, nullptr, nullptr, n2H, n2L, 128);
    // 11. r1 = relu(nf2 @ wr^T + br)                         [N,256] K=128
    tg<1,0,0><<<dim3(2, MT), blk, TG_SMEM>>>(n2H, n2L, nullptr, nullptr, 128,
                                             wrH, wrL, nullptr, nullptr, 128, 128,
                                             br, nullptr, nullptr, r1H, r1L, 256);
    // 12. logits = r1 @ wr2^T + br2                          [N,8]
    logits_kernel<<<NN / 32, blk>>>(r1H, r1L, wr2, br2, logits);
}

// round 17
// speedup vs baseline: 1.1584x; 1.0571x over previous
#include <cuda_runtime.h>
#include <cuda_bf16.h>
#include <math.h>
#include <stdint.h>

#define NN 65536
#define EE 524288
// dims: OBS=256 HID=512 MID=256 LSTM=256 DOUT=128 DLAST=128 RFM=256 LH=256 ACT=8

typedef __nv_bfloat16 bf16;

// ---------------- scratch (device globals; no allocation allowed) -------------
__device__ __align__(16) bf16 g_obsH[NN * 256], g_obsL[NN * 256];
__device__ __align__(16) bf16 g_h0H[NN * 256],  g_h0L[NN * 256];
__device__ __align__(16) bf16 g_t1H[NN * 512],  g_t1L[NN * 512];
__device__ __align__(16) bf16 g_xH[NN * 256],   g_xL[NN * 256];
__device__ __align__(16) bf16 g_rhH[NN * 256],  g_rhL[NN * 256];
__device__ __align__(16) bf16 g_nfH[NN * 128],  g_nfL[NN * 128];
__device__ __align__(16) bf16 g_UVH[NN * 512],  g_UVL[NN * 512];   // [U | V]
__device__ __align__(16) bf16 g_aHH[NN * 256],  g_aHL[NN * 256];
__device__ __align__(16) bf16 g_aEH[NN * 128],  g_aEL[NN * 128];
__device__ __align__(16) bf16 g_nhH[NN * 256],  g_nhL[NN * 256];
__device__ __align__(16) bf16 g_n2H[NN * 128],  g_n2L[NN * 128];
__device__ __align__(16) bf16 g_r1H[NN * 256],  g_r1L[NN * 256];
// weight planes (wih/whh gate-interleaved row' = unit*4+gate; wuv = [weL;weR])
__device__ __align__(16) bf16 g_w1aH[512 * 256],  g_w1aL[512 * 256];
__device__ __align__(16) bf16 g_w1bH[256 * 512],  g_w1bL[256 * 512];
__device__ __align__(16) bf16 g_wihH[1024 * 256], g_wihL[1024 * 256];
__device__ __align__(16) bf16 g_whhH[1024 * 256], g_whhL[1024 * 256];
__device__ __align__(16) bf16 g_w1H[128 * 256],   g_w1L[128 * 256];
__device__ __align__(16) bf16 g_wuvH[512 * 128],  g_wuvL[512 * 128];
__device__ __align__(16) bf16 g_we2H[128 * 256],  g_we2L[128 * 256];
__device__ __align__(16) bf16 g_wnH[256 * 256],   g_wnL[256 * 256];
__device__ __align__(16) bf16 g_wn2H[128 * 256],  g_wn2L[128 * 256];
__device__ __align__(16) bf16 g_wrH[256 * 128],   g_wrL[256 * 128];
__device__ float g_bg[1024];         // permuted combined gate bias
__device__ float g_buv[512];         // [be | 0]
// misc
__device__ float g_deg[NN];
__device__ int g_cnt[NN];
__device__ int g_csr[NN];
__device__ int g_cur[NN];
__device__ int g_srcv[EE];
__device__ int g_bsum[256];

// ---------------------------- helpers -----------------------------------------
__device__ __forceinline__ uint32_t sm2u(const void* p) {
    return (uint32_t)__cvta_generic_to_shared(p);
}
__device__ __forceinline__ uint32_t pk(bf16 a, bf16 b) {
    return (uint32_t)__bfloat16_as_ushort(a) |
           ((uint32_t)__bfloat16_as_ushort(b) << 16);
}
__device__ __forceinline__ void split2(float a, float b, uint32_t& hi, uint32_t& lo) {
    const bf16 ha = __float2bfloat16_rn(a), hb = __float2bfloat16_rn(b);
    hi = pk(ha, hb);
    lo = pk(__float2bfloat16_rn(a - __bfloat162float(ha)),
            __float2bfloat16_rn(b - __bfloat162float(hb)));
}
__device__ __forceinline__ void mma16(float* d, const uint32_t* a, const uint32_t* b) {
    asm volatile(
        "mma.sync.aligned.m16n8k16.row.col.f32.bf16.bf16.f32 "
        "{%0,%1,%2,%3}, {%4,%5,%6,%7}, {%8,%9}, {%0,%1,%2,%3};"
        : "+f"(d[0]), "+f"(d[1]), "+f"(d[2]), "+f"(d[3])
        : "r"(a[0]), "r"(a[1]), "r"(a[2]), "r"(a[3]), "r"(b[0]), "r"(b[1]));
}
__device__ __forceinline__ void ldsm4(uint32_t* r, uint32_t addr) {
    asm volatile(
        "ldmatrix.sync.aligned.m8n8.x4.shared.b16 {%0,%1,%2,%3}, [%4];"
        : "=r"(r[0]), "=r"(r[1]), "=r"(r[2]), "=r"(r[3]) : "r"(addr));
}
__device__ __forceinline__ void cpa16(uint32_t s, const void* g) {
    asm volatile("cp.async.cg.shared.global [%0], [%1], 16;" :: "r"(s), "l"(g));
}
__device__ __forceinline__ void cpcommit() {
    asm volatile("cp.async.commit_group;" ::: "memory");
}
template <int N>
__device__ __forceinline__ void cpwait() {
    asm volatile("cp.async.wait_group %0;" :: "n"(N) : "memory");
}
__device__ __forceinline__ float sigm(float x) {
    return __fdividef(1.f, 1.f + __expf(-x));
}
__device__ __forceinline__ float ftanh(float x) {
    const float e = __expf(2.f * x);
    return __fdividef(e - 1.f, e + 1.f);
}

// =============================================================================
// Shared GEMM core (BM=128, BN=128, BK=32; 256 thr = 8 warps 4m x 2n)
// 80KB smem => 2 CTAs/SM resident — the measured-best configuration (R11).
// =============================================================================
#define AP 40
#define STG_ELT 20480              // bf16 elements per stage (40960 B)
#define TG_SMEM (2 * STG_ELT * 2)  // 81920 bytes

__device__ __forceinline__ void tg_issue(
    const bf16* pAh, const bf16* pAl, int ldA, int rowBase,
    const bf16* pWh, const bf16* pWl, int ldW, int colBase,
    int kk0, bf16* sb, int tid)
{
#pragma unroll
    for (int i = 0; i < 2; i++) {
        const int idx = tid + 256 * i;
        const int r = idx >> 2, c8 = (idx & 3) * 8;
        const int so = r * AP + c8;
        cpa16(sm2u(sb + so),        pAh + (size_t)(rowBase + r) * ldA + kk0 + c8);
        cpa16(sm2u(sb + 5120 + so), pAl + (size_t)(rowBase + r) * ldA + kk0 + c8);
        cpa16(sm2u(sb + 10240 + so), pWh + (size_t)(colBase + r) * ldW + kk0 + c8);
        cpa16(sm2u(sb + 15360 + so), pWl + (size_t)(colBase + r) * ldW + kk0 + c8);
    }
    cpcommit();
}

#define TG_MAINLOOP(ACC, DUAL_)                                                   \
    const int ncp = K >> 5, total = (DUAL_) ? 2 * ncp : ncp;                      \
    tg_issue(Ah_, Al_, ldA, rowBase, Wh_, Wl_, ldW, colBase, 0, sm, tid);         \
    _Pragma("unroll 1")                                                           \
    for (int c = 0; c < total; c++) {                                             \
        if (c + 1 < total) {                                                      \
            const int n = c + 1;                                                  \
            const int ph = (DUAL_) ? (n >= ncp) : 0;                              \
            tg_issue(ph ? A2h : Ah_, ph ? A2l : Al_, ldA, rowBase,                \
                     ph ? W2h : Wh_, ph ? W2l : Wl_, ldW, colBase,                \
                     (ph ? n - ncp : n) << 5, sm + (n & 1) * STG_ELT, tid);       \
            cpwait<1>();                                                          \
        } else {                                                                  \
            cpwait<0>();                                                          \
        }                                                                         \
        __syncthreads();                                                          \
        const uint32_t base = sm2u(sm) + (uint32_t)(c & 1) * (STG_ELT * 2);       \
        _Pragma("unroll")                                                         \
        for (int kk = 0; kk < 32; kk += 16) {                                     \
            uint32_t ah[2][4], al[2][4], bh[4][4], bl[4][4];                      \
            _Pragma("unroll")                                                     \
            for (int mt = 0; mt < 2; mt++) {                                      \
                const uint32_t off =                                              \
                    (uint32_t)((wy * 32 + mt * 16 + (lane & 15)) * AP +           \
                               kk + ((lane >> 4) << 3)) * 2;                      \
                ldsm4(ah[mt], base + off);                                        \
                ldsm4(al[mt], base + 10240 + off);                                \
            }                                                                     \
            _Pragma("unroll")                                                     \
            for (int nb = 0; nb < 4; nb++) {                                      \
                const uint32_t off =                                              \
                    (uint32_t)((wx * 64 + nb * 16 + (lane & 7) +                  \
                                (((lane >> 4) & 1) << 3)) * AP +                  \
                               kk + (((lane >> 3) & 1) << 3)) * 2;                \
                ldsm4(bh[nb], base + 20480 + off);                                \
                ldsm4(bl[nb], base + 30720 + off);                                \
            }                                                                     \
            _Pragma("unroll")                                                     \
            for (int mt = 0; mt < 2; mt++)                                        \
                _Pragma("unroll")                                                 \
                for (int nb = 0; nb < 4; nb++)                                    \
                    _Pragma("unroll")                                             \
                    for (int h = 0; h < 2; h++) {                                 \
                        mma16(ACC[mt][nb][h], ah[mt], &bh[nb][2 * h]);            \
                        mma16(ACC[mt][nb][h], ah[mt], &bl[nb][2 * h]);            \
                        mma16(ACC[mt][nb][h], al[mt], &bh[nb][2 * h]);            \
                    }                                                             \
        }                                                                         \
        __syncthreads();                                                          \
    }

// =============================================================================
// Generic GEMM: C = act(A@W^T [+ A2@W2^T] + bias [+bias2]) -> hi/lo planes
// =============================================================================
template <int RELU_OUT, int DEGBIAS, int DUAL>
__global__ __launch_bounds__(256) void tg(
    const bf16* __restrict__ Ah_, const bf16* __restrict__ Al_,
    const bf16* __restrict__ A2h, const bf16* __restrict__ A2l, int ldA,
    const bf16* __restrict__ Wh_, const bf16* __restrict__ Wl_,
    const bf16* __restrict__ W2h, const bf16* __restrict__ W2l, int ldW, int K,
    const float* __restrict__ bias, const float* __restrict__ bias2,
    const float* __restrict__ deg,
    bf16* __restrict__ Ch, bf16* __restrict__ Cl, int ldC)
{
    extern __shared__ bf16 sm[];
    const int tid = threadIdx.x, warp = tid >> 5, lane = tid & 31;
    const int wy = warp >> 1, wx = warp & 1;
    const int g = lane >> 2, tg2 = lane & 3;
    const int rowBase = blockIdx.y * 128, colBase = blockIdx.x * 128;

    float acc[2][4][2][4];
#pragma unroll
    for (int a = 0; a < 2; a++)
#pragma unroll
        for (int b = 0; b < 4; b++)
#pragma unroll
            for (int c = 0; c < 2; c++)
#pragma unroll
                for (int d = 0; d < 4; d++) acc[a][b][c][d] = 0.f;

    TG_MAINLOOP(acc, DUAL)

#pragma unroll
    for (int mt = 0; mt < 2; mt++) {
        const int row = rowBase + wy * 32 + mt * 16 + g;
        const float d0 = DEGBIAS ? deg[row] : 1.f;
        const float d1 = DEGBIAS ? deg[row + 8] : 1.f;
#pragma unroll
        for (int nb = 0; nb < 4; nb++)
#pragma unroll
            for (int h = 0; h < 2; h++) {
                const int col = colBase + wx * 64 + nb * 16 + h * 8 + 2 * tg2;
                float bb0 = 0.f, bb1 = 0.f;
                if (bias)  { bb0 = bias[col];  bb1 = bias[col + 1]; }
                if (DUAL && bias2) { bb0 += bias2[col]; bb1 += bias2[col + 1]; }
                float v0 = acc[mt][nb][h][0] + d0 * bb0;
                float v1 = acc[mt][nb][h][1] + d0 * bb1;
                float v2 = acc[mt][nb][h][2] + d1 * bb0;
                float v3 = acc[mt][nb][h][3] + d1 * bb1;
                if (RELU_OUT) {
                    v0 = fmaxf(v0, 0.f); v1 = fmaxf(v1, 0.f);
                    v2 = fmaxf(v2, 0.f); v3 = fmaxf(v3, 0.f);
                }
                uint32_t hi, lo;
                split2(v0, v1, hi, lo);
                *(uint32_t*)&Ch[(size_t)row * ldC + col] = hi;
                *(uint32_t*)&Cl[(size_t)row * ldC + col] = lo;
                split2(v2, v3, hi, lo);
                *(uint32_t*)&Ch[(size_t)(row + 8) * ldC + col] = hi;
                *(uint32_t*)&Cl[(size_t)(row + 8) * ldC + col] = lo;
            }
    }
}

// =============================================================================
// Fused gates GEMM + LSTM (weights gate-interleaved; tile = 128 rows x 32 units)
// =============================================================================
#define EPI_PITCH 132

__global__ __launch_bounds__(256) void tglstm(
    const bf16* __restrict__ Ah_, const bf16* __restrict__ Al_,
    const bf16* __restrict__ A2h, const bf16* __restrict__ A2l, int ldA,
    const bf16* __restrict__ Wh_, const bf16* __restrict__ Wl_,
    const bf16* __restrict__ W2h, const bf16* __restrict__ W2l, int ldW, int K,
    const float* __restrict__ bgate,
    const float* __restrict__ c0,
    float* __restrict__ h1, float* __restrict__ c1,
    bf16* __restrict__ rhh, bf16* __restrict__ rhl)
{
    extern __shared__ bf16 sm[];
    const int tid = threadIdx.x, warp = tid >> 5, lane = tid & 31;
    const int wy = warp >> 1, wx = warp & 1;
    const int g = lane >> 2, tg2 = lane & 3;
    const int rowBase = blockIdx.y * 128, colBase = blockIdx.x * 128;

    float acc[2][4][2][4];
#pragma unroll
    for (int a = 0; a < 2; a++)
#pragma unroll
        for (int b = 0; b < 4; b++)
#pragma unroll
            for (int c = 0; c < 2; c++)
#pragma unroll
                for (int d = 0; d < 4; d++) acc[a][b][c][d] = 0.f;

    TG_MAINLOOP(acc, 1)

    float* st = (float*)sm;
#pragma unroll
    for (int mt = 0; mt < 2; mt++) {
        const int row = wy * 32 + mt * 16 + g;
#pragma unroll
        for (int nb = 0; nb < 4; nb++)
#pragma unroll
            for (int h = 0; h < 2; h++) {
                const int col = wx * 64 + nb * 16 + h * 8 + 2 * tg2;
                const float b0 = bgate[colBase + col];
                const float b1 = bgate[colBase + col + 1];
                st[row * EPI_PITCH + col]           = acc[mt][nb][h][0] + b0;
                st[row * EPI_PITCH + col + 1]       = acc[mt][nb][h][1] + b1;
                st[(row + 8) * EPI_PITCH + col]     = acc[mt][nb][h][2] + b0;
                st[(row + 8) * EPI_PITCH + col + 1] = acc[mt][nb][h][3] + b1;
            }
    }
    __syncthreads();

    const int uBase = colBase >> 2;
#pragma unroll
    for (int i = 0; i < 16; i++) {
        const int idx = tid + 256 * i;
        const int r = idx >> 5, u = idx & 31;
        const float* gp = st + r * EPI_PITCH + u * 4;
        const float ig = sigm(gp[0]);
        const float fg = sigm(gp[1]);
        const float gg = ftanh(gp[2]);
        const float og = sigm(gp[3]);
        const size_t o = (size_t)(rowBase + r) * 256 + uBase + u;
        const float cv = fg * c0[o] + ig * gg;
        const float hv = og * ftanh(cv);
        c1[o] = cv;
        h1[o] = hv;
        const float rv = fmaxf(hv, 0.f);
        const bf16 hb = __float2bfloat16_rn(rv);
        rhh[o] = hb;
        rhl[o] = __float2bfloat16_rn(rv - __bfloat162float(hb));
    }
}

// =============================================================================
// megasplit: plane splits / permutes / biases in one kernel (cnt zero moved
// to the CSR side stream). modes: 0 plain split, 1 gate-perm, 2 we->[weL;weR],
// 4 gate bias (bg), 5 uv bias ([be|0])
// =============================================================================
struct Seg { const void* in; void* hi; void* lo; int n; int mode; };
struct SegT { Seg s[16]; int nseg; int total; };

__global__ __launch_bounds__(256) void megasplit(SegT T)
{
    for (int idx = blockIdx.x * 256 + threadIdx.x; idx < T.total;
         idx += gridDim.x * 256) {
        int i = idx, k = 0;
        while (i >= T.s[k].n) { i -= T.s[k].n; k++; }
        const Seg sg = T.s[k];
        if (sg.mode == 0) {
            const float4 v = ((const float4*)sg.in)[i];
            uint32_t h0, l0, h1, l1;
            split2(v.x, v.y, h0, l0);
            split2(v.z, v.w, h1, l1);
            ((uint2*)sg.hi)[i] = make_uint2(h0, h1);
            ((uint2*)sg.lo)[i] = make_uint2(l0, l1);
        } else if (sg.mode == 1) {
            const int r = i >> 6, c = i & 63;
            const int rp = (r & 255) * 4 + (r >> 8);
            const float4 v = ((const float4*)sg.in)[i];
            uint32_t h0, l0, h1, l1;
            split2(v.x, v.y, h0, l0);
            split2(v.z, v.w, h1, l1);
            ((uint2*)sg.hi)[rp * 64 + c] = make_uint2(h0, h1);
            ((uint2*)sg.lo)[rp * 64 + c] = make_uint2(l0, l1);
        } else if (sg.mode == 2) {
            const int r = i >> 6, c4 = i & 63;
            const int orow = (c4 < 32) ? r : 256 + r;
            const int oidx = orow * 32 + (c4 & 31);
            const float4 v = ((const float4*)sg.in)[i];
            uint32_t h0, l0, h1, l1;
            split2(v.x, v.y, h0, l0);
            split2(v.z, v.w, h1, l1);
            ((uint2*)sg.hi)[oidx] = make_uint2(h0, h1);
            ((uint2*)sg.lo)[oidx] = make_uint2(l0, l1);
        } else if (sg.mode == 4) {
            const float b = ((const float*)sg.in)[i] + ((const float*)sg.lo)[i];
            ((float*)sg.hi)[(i & 255) * 4 + (i >> 8)] = b;
        } else {
            ((float*)sg.hi)[i] = (i < 256) ? ((const float*)sg.in)[i] : 0.f;
        }
    }
}

// =============================================================================
// CSR build (runs on the side stream, overlapped with megasplit + GEMMs 1-6)
// =============================================================================
__global__ __launch_bounds__(256) void zero_int_kernel(int* __restrict__ p)
{
    p[blockIdx.x * 256 + threadIdx.x] = 0;
}
__global__ __launch_bounds__(256) void hist_kernel(const int* __restrict__ dst,
                                                   int* __restrict__ cnt)
{
    atomicAdd(&cnt[dst[blockIdx.x * 256 + threadIdx.x]], 1);
}
__global__ __launch_bounds__(256) void scan1_kernel(
    const int* __restrict__ cnt, int* __restrict__ csr, int* __restrict__ bsum)
{
    __shared__ int s[256];
    const int t = threadIdx.x, b = blockIdx.x;
    const int v = cnt[b * 256 + t];
    s[t] = v; __syncthreads();
#pragma unroll
    for (int off = 1; off < 256; off <<= 1) {
        int x = (t >= off) ? s[t - off] : 0;
        __syncthreads();
        s[t] += x;
        __syncthreads();
    }
    csr[b * 256 + t] = s[t] - v;
    if (t == 255) bsum[b] = s[255];
}
__global__ __launch_bounds__(256) void scan3_kernel(
    int* __restrict__ csr, const int* __restrict__ bsum, int* __restrict__ cur)
{
    __shared__ int s[256];
    const int t = threadIdx.x, b = blockIdx.x;
    const int v = bsum[t];
    s[t] = v; __syncthreads();
#pragma unroll
    for (int off = 1; off < 256; off <<= 1) {
        int x = (t >= off) ? s[t - off] : 0;
        __syncthreads();
        s[t] += x;
        __syncthreads();
    }
    const int prefix = s[b] - bsum[b];
    const int i = b * 256 + t;
    const int x = csr[i] + prefix;
    csr[i] = x;
    cur[i] = x;
}
__global__ __launch_bounds__(256) void scatter_src_kernel(
    const int* __restrict__ dst, const int* __restrict__ src,
    int* __restrict__ cur, int* __restrict__ srcv)
{
    const int e = blockIdx.x * 256 + threadIdx.x;
    const int p = atomicAdd(&cur[dst[e]], 1);
    srcv[p] = src[e];
}

// =============================================================================
// Edge gather (R11 warp-per-node): aggH[d] = sum relu(U[s]+V[d]); deg=cnt
// =============================================================================
__device__ __forceinline__ void unpack8(uint4 h, uint4 l, float* o) {
    const __nv_bfloat162* hp = (const __nv_bfloat162*)&h;
    const __nv_bfloat162* lp = (const __nv_bfloat162*)&l;
#pragma unroll
    for (int j = 0; j < 4; j++) {
        const float2 fh = __bfloat1622float2(hp[j]);
        const float2 fl = __bfloat1622float2(lp[j]);
        o[2 * j] = fh.x + fl.x;
        o[2 * j + 1] = fh.y + fl.y;
    }
}

__global__ __launch_bounds__(256) void gather_kernel(
    const bf16* __restrict__ UVh, const bf16* __restrict__ UVl,
    const int* __restrict__ srcv,
    const int* __restrict__ csr, const int* __restrict__ cnt,
    bf16* __restrict__ aggHh, bf16* __restrict__ aggHl, float* __restrict__ deg)
{
    const int d = blockIdx.x * 8 + (threadIdx.x >> 5);
    const int l = threadIdx.x & 31;
    const int start = csr[d];
    const int n = cnt[d];

    float v[8];
    unpack8(((const uint4*)(UVh + (size_t)d * 512 + 256))[l],
            ((const uint4*)(UVl + (size_t)d * 512 + 256))[l], v);
    float a[8];
#pragma unroll
    for (int j = 0; j < 8; j++) a[j] = 0.f;

    const int nw = n < 32 ? n : 32;
    int myS = 0;
    if (l < nw) myS = srcv[start + l];
    for (int i = 0; i < nw; i++) {
        const int s = __shfl_sync(0xffffffffu, myS, i);
        float u[8];
        unpack8(((const uint4*)(UVh + (size_t)s * 512))[l],
                ((const uint4*)(UVl + (size_t)s * 512))[l], u);
#pragma unroll
        for (int j = 0; j < 8; j++) a[j] += fmaxf(u[j] + v[j], 0.f);
    }
    for (int i = 32; i < n; i++) {
        const int s = srcv[start + i];
        float u[8];
        unpack8(((const uint4*)(UVh + (size_t)s * 512))[l],
                ((const uint4*)(UVl + (size_t)s * 512))[l], u);
#pragma unroll
        for (int j = 0; j < 8; j++) a[j] += fmaxf(u[j] + v[j], 0.f);
    }

    uint4 oh, ol;
    split2(a[0], a[1], oh.x, ol.x);
    split2(a[2], a[3], oh.y, ol.y);
    split2(a[4], a[5], oh.z, ol.z);
    split2(a[6], a[7], oh.w, ol.w);
    ((uint4*)(aggHh + (size_t)d * 256))[l] = oh;
    ((uint4*)(aggHl + (size_t)d * 256))[l] = ol;
    if (l == 0) deg[d] = (float)n;
}

// =============================================================================
// Readout second layer
// =============================================================================
__global__ __launch_bounds__(256) void logits_kernel(
    const bf16* __restrict__ r1h, const bf16* __restrict__ r1l,
    const float* __restrict__ wr2, const float* __restrict__ br2,
    float* __restrict__ out)
{
    __shared__ float sw[8 * 257];
    const int tid = threadIdx.x;
    for (int i = tid; i < 2048; i += 256)
        sw[(i >> 8) * 257 + (i & 255)] = wr2[i];
    __syncthreads();

    const int row = blockIdx.x * 32 + (tid >> 3);
    const int o = tid & 7;
    const __nv_bfloat162* ah = (const __nv_bfloat162*)(r1h + (size_t)row * 256);
    const __nv_bfloat162* al = (const __nv_bfloat162*)(r1l + (size_t)row * 256);
    const float* w = sw + o * 257;
    float acc = 0.f;
#pragma unroll 8
    for (int k = 0; k < 128; k++) {
        const float2 h = __bfloat1622float2(ah[k]);
        const float2 l = __bfloat1622float2(al[k]);
        acc = fmaf(h.x + l.x, w[2 * k], acc);
        acc = fmaf(h.y + l.y, w[2 * k + 1], acc);
    }
    out[(size_t)row * 8 + o] = acc + br2[o];
}

// =============================================================================
// Launcher
// =============================================================================
#define GSYM(var, sym) cudaGetSymbolAddress((void**)&var, sym)

extern "C" void kernel_launch(void* const* d_in, const int* in_sizes, int n_in,
                              void* d_out, int out_size)
{
    const float* obs  = (const float*)d_in[0];
    const float* h0   = (const float*)d_in[1];
    const float* c0   = (const float*)d_in[2];
    const int*   src  = (const int*)d_in[3];
    const int*   dst  = (const int*)d_in[4];
    const float* w1a  = (const float*)d_in[5];
    const float* b1a  = (const float*)d_in[6];
    const float* w1b  = (const float*)d_in[7];
    const float* b1b  = (const float*)d_in[8];
    const float* w_ih = (const float*)d_in[9];
    const float* b_ih = (const float*)d_in[10];
    const float* w_hh = (const float*)d_in[11];
    const float* b_hh = (const float*)d_in[12];
    const float* w1   = (const float*)d_in[13];
    const float* b1   = (const float*)d_in[14];
    const float* we   = (const float*)d_in[15];
    const float* be   = (const float*)d_in[16];
    const float* we2  = (const float*)d_in[17];
    const float* be2  = (const float*)d_in[18];
    const float* wn   = (const float*)d_in[19];
    const float* bn   = (const float*)d_in[20];
    const float* wn2  = (const float*)d_in[21];
    const float* bn2  = (const float*)d_in[22];
    const float* wr   = (const float*)d_in[23];
    const float* br   = (const float*)d_in[24];
    const float* wr2  = (const float*)d_in[25];
    const float* br2  = (const float*)d_in[26];

    float* out    = (float*)d_out;
    float* logits = out;                       // [N, 8]
    float* h1     = out + (size_t)NN * 8;      // [N, 256]
    float* c1     = h1 + (size_t)NN * 256;     // [N, 256]

    bf16 *obsH, *obsL, *h0H, *h0L, *t1H, *t1L, *xH, *xL, *rhH, *rhL,
         *nfH, *nfL, *UVH, *UVL, *aHH, *aHL, *aEH, *aEL, *nhH, *nhL,
         *n2H, *n2L, *r1H, *r1L;
    bf16 *w1aH, *w1aL, *w1bH, *w1bL, *wihH, *wihL, *whhH, *whhL, *w1H, *w1L,
         *wuvH, *wuvL, *we2H, *we2L, *wnH, *wnL, *wn2H, *wn2L, *wrH, *wrL;
    float *p_deg, *p_bg, *p_buv;
    int *p_cnt, *p_csr, *p_cur, *p_srcv, *p_bsum;

    GSYM(obsH, g_obsH); GSYM(obsL, g_obsL); GSYM(h0H, g_h0H); GSYM(h0L, g_h0L);
    GSYM(t1H, g_t1H);   GSYM(t1L, g_t1L);   GSYM(xH, g_xH);   GSYM(xL, g_xL);
    GSYM(rhH, g_rhH);   GSYM(rhL, g_rhL);
    GSYM(nfH, g_nfH);   GSYM(nfL, g_nfL);   GSYM(UVH, g_UVH); GSYM(UVL, g_UVL);
    GSYM(aHH, g_aHH);   GSYM(aHL, g_aHL);
    GSYM(aEH, g_aEH);   GSYM(aEL, g_aEL);   GSYM(nhH, g_nhH); GSYM(nhL, g_nhL);
    GSYM(n2H, g_n2H);   GSYM(n2L, g_n2L);   GSYM(r1H, g_r1H); GSYM(r1L, g_r1L);
    GSYM(w1aH, g_w1aH); GSYM(w1aL, g_w1aL); GSYM(w1bH, g_w1bH); GSYM(w1bL, g_w1bL);
    GSYM(wihH, g_wihH); GSYM(wihL, g_wihL); GSYM(whhH, g_whhH); GSYM(whhL, g_whhL);
    GSYM(w1H, g_w1H);   GSYM(w1L, g_w1L);   GSYM(wuvH, g_wuvH); GSYM(wuvL, g_wuvL);
    GSYM(we2H, g_we2H); GSYM(we2L, g_we2L); GSYM(wnH, g_wnH);   GSYM(wnL, g_wnL);
    GSYM(wn2H, g_wn2H); GSYM(wn2L, g_wn2L); GSYM(wrH, g_wrH);   GSYM(wrL, g_wrL);
    GSYM(p_bg, g_bg);   GSYM(p_buv, g_buv); GSYM(p_deg, g_deg);
    GSYM(p_cnt, g_cnt); GSYM(p_csr, g_csr); GSYM(p_cur, g_cur);
    GSYM(p_srcv, g_srcv); GSYM(p_bsum, g_bsum);

    cudaFuncSetAttribute(tg<1,0,0>, cudaFuncAttributeMaxDynamicSharedMemorySize, TG_SMEM);
    cudaFuncSetAttribute(tg<0,0,0>, cudaFuncAttributeMaxDynamicSharedMemorySize, TG_SMEM);
    cudaFuncSetAttribute(tg<0,1,0>, cudaFuncAttributeMaxDynamicSharedMemorySize, TG_SMEM);
    cudaFuncSetAttribute(tg<1,0,1>, cudaFuncAttributeMaxDynamicSharedMemorySize, TG_SMEM);
    cudaFuncSetAttribute(tglstm, cudaFuncAttributeMaxDynamicSharedMemorySize, TG_SMEM);

    const dim3 blk(256);
    const int MT = NN / 128;   // 512 row tiles

    // ---- fork a side stream for the CSR build (joined before gather) ----
    // Created per call and leaked deliberately: kernel_launch only runs for the
    // correctness pass + graph capture; destroying a capture-joined stream
    // before EndCapture is illegal.
    cudaStream_t s2;
    cudaStreamCreateWithFlags(&s2, cudaStreamNonBlocking);
    cudaEvent_t evF, evJ;
    cudaEventCreateWithFlags(&evF, cudaEventDisableTiming);
    cudaEventCreateWithFlags(&evJ, cudaEventDisableTiming);

    cudaEventRecord(evF, 0);
    cudaStreamWaitEvent(s2, evF, 0);
    zero_int_kernel<<<NN / 256, blk, 0, s2>>>(p_cnt);
    hist_kernel<<<EE / 256, blk, 0, s2>>>(dst, p_cnt);
    scan1_kernel<<<256, blk, 0, s2>>>(p_cnt, p_csr, p_bsum);
    scan3_kernel<<<256, blk, 0, s2>>>(p_csr, p_bsum, p_cur);
    scatter_src_kernel<<<EE / 256, blk, 0, s2>>>(dst, src, p_cur, p_srcv);
    cudaEventRecord(evJ, s2);

    // ---- main stream: megasplit (weights + obs/h0 planes + biases) ----
    SegT T;
    int seg = 0, tot = 0;
    auto addseg = [&](const void* in, void* hi, void* lo, int n, int mode) {
        T.s[seg].in = in; T.s[seg].hi = hi; T.s[seg].lo = lo;
        T.s[seg].n = n; T.s[seg].mode = mode;
        seg++; tot += n;
    };
    addseg(obs, obsH, obsL, NN * 256 / 4, 0);
    addseg(h0, h0H, h0L, NN * 256 / 4, 0);
    addseg(w_ih, wihH, wihL, 1024 * 256 / 4, 1);
    addseg(w_hh, whhH, whhL, 1024 * 256 / 4, 1);
    addseg(w1a, w1aH, w1aL, 512 * 256 / 4, 0);
    addseg(w1b, w1bH, w1bL, 256 * 512 / 4, 0);
    addseg(we, wuvH, wuvL, 256 * 256 / 4, 2);
    addseg(wn, wnH, wnL, 256 * 256 / 4, 0);
    addseg(w1, w1H, w1L, 128 * 256 / 4, 0);
    addseg(we2, we2H, we2L, 128 * 256 / 4, 0);
    addseg(wn2, wn2H, wn2L, 128 * 256 / 4, 0);
    addseg(wr, wrH, wrL, 256 * 128 / 4, 0);
    addseg(b_ih, p_bg, (void*)b_hh, 1024, 4);
    addseg(be, p_buv, nullptr, 512, 5);
    T.nseg = seg; T.total = tot;
    megasplit<<<2048, blk>>>(T);

    // 1. t1 = relu(obs @ w1a^T + b1a)                        [N,512] K=256
    tg<1,0,0><<<dim3(4, MT), blk, TG_SMEM>>>(obsH, obsL, nullptr, nullptr, 256,
                                             w1aH, w1aL, nullptr, nullptr, 256, 256,
                                             b1a, nullptr, nullptr, t1H, t1L, 512);
    // 2. x = t1 @ w1b^T + b1b                                [N,256] K=512
    tg<0,0,0><<<dim3(2, MT), blk, TG_SMEM>>>(t1H, t1L, nullptr, nullptr, 512,
                                             w1bH, w1bL, nullptr, nullptr, 512, 512,
                                             b1b, nullptr, nullptr, xH, xL, 256);
    // 3+4. fused gates GEMM + LSTM -> h1, c1, relu(h1) planes
    tglstm<<<dim3(8, MT), blk, TG_SMEM>>>(xH, xL, h0H, h0L, 256,
                                          wihH, wihL, whhH, whhL, 256, 256,
                                          p_bg, c0, h1, c1, rhH, rhL);
    // 5. nf = relu(h1) @ w1^T + b1                           [N,128] K=256
    tg<0,0,0><<<dim3(1, MT), blk, TG_SMEM>>>(rhH, rhL, nullptr, nullptr, 256,
                                             w1H, w1L, nullptr, nullptr, 256, 256,
                                             b1, nullptr, nullptr, nfH, nfL, 128);
    // 6. [U|V] = nf @ wuv^T + [be|0]                         [N,512] K=128
    tg<0,0,0><<<dim3(4, MT), blk, TG_SMEM>>>(nfH, nfL, nullptr, nullptr, 128,
                                             wuvH, wuvL, nullptr, nullptr, 128, 128,
                                             p_buv, nullptr, nullptr, UVH, UVL, 512);
    // join CSR stream, then gather
    cudaStreamWaitEvent(0, evJ, 0);
    // 7. gather: aggH[d] = sum relu(U[src]+V[d]); deg[d]=cnt[d]
    gather_kernel<<<NN / 8, blk>>>(UVH, UVL, p_srcv, p_csr, p_cnt,
                                   aHH, aHL, p_deg);
    // 8. aggE = aggH @ we2^T + deg*be2                       [N,128] K=256
    tg<0,1,0><<<dim3(1, MT), blk, TG_SMEM>>>(aHH, aHL, nullptr, nullptr, 256,
                                             we2H, we2L, nullptr, nullptr, 256, 256,
                                             be2, nullptr, p_deg, aEH, aEL, 128);
    // 9. nh = relu(nf@wnL^T + aggE@wnR^T + bn)               [N,256]
    tg<1,0,1><<<dim3(2, MT), blk, TG_SMEM>>>(nfH, nfL, aEH, aEL, 128,
                                             wnH, wnL, wnH + 128, wnL + 128, 256, 128,
                                             bn, nullptr, nullptr, nhH, nhL, 256);
    // 10. nf2 = nh @ wn2^T + bn2                             [N,128] K=256
    tg<0,0,0><<<dim3(1, MT), blk, TG_SMEM>>>(nhH, nhL, nullptr, nullptr, 256,
                                             wn2H, wn2L, nullptr, nullptr, 256, 256,
                                             bn2, nullptr, nullptr, n2H, n2L, 128);
    // 11. r1 = relu(nf2 @ wr^T + br)                         [N,256] K=128
    tg<1,0,0><<<dim3(2, MT), blk, TG_SMEM>>>(n2H, n2L, nullptr, nullptr, 128,
                                             wrH, wrL, nullptr, nullptr, 128, 128,
                                             br, nullptr, nullptr, r1H, r1L, 256);
    // 12. logits = r1 @ wr2^T + br2                          [N,8]
    logits_kernel<<<NN / 32, blk>>>(r1H, r1L, wr2, br2, logits);
}